// round 3
// baseline (speedup 1.0000x reference)
#include <cuda_runtime.h>
#include <math.h>
#include <float.h>

#define Bb 8
#define Tt 256
#define NPOS (Bb*Tt)     // 2048
#define IDIM 80
#define HDIM 256
#define CDIM 64
#define NIT 4
#define TPB 256
#define NSHIFT 159
#define NSENC 81
#define ETH_I 40

typedef unsigned long long u64;

__device__ float g_partial[NPOS];

// ---------------- f32x2 helpers ----------------
__device__ __forceinline__ u64 dup2(float x) {
    u64 r; asm("mov.b64 %0, {%1, %1};" : "=l"(r) : "f"(x)); return r;
}
__device__ __forceinline__ void fma2(u64& acc, u64 a, u64 b) {
    asm("fma.rn.f32x2 %0, %1, %2, %0;" : "+l"(acc) : "l"(a), "l"(b));
}
__device__ __forceinline__ void unpk(u64 v, float& lo, float& hi) {
    asm("mov.b64 {%0, %1}, %2;" : "=f"(lo), "=f"(hi) : "l"(v));
}
__device__ __forceinline__ u64 lds64(const float* base, int pairIdx) {
    return *reinterpret_cast<const u64*>(base + 2 * pairIdx);
}

// ---------------- reductions (deterministic) ----------------
__device__ __forceinline__ float warpSum(float v) {
#pragma unroll
    for (int o = 16; o > 0; o >>= 1) v += __shfl_down_sync(0xffffffffu, v, o);
    return v;
}

__device__ __forceinline__ float blockSum(float v, float* buf) {
    v = warpSum(v);
    int w = threadIdx.x >> 5, l = threadIdx.x & 31;
    if (l == 0) buf[w] = v;
    __syncthreads();
    if (threadIdx.x == 0) {
        float s = 0.f;
#pragma unroll
        for (int i = 0; i < 8; i++) s += buf[i];
        buf[0] = s;
    }
    __syncthreads();
    float r = buf[0];
    __syncthreads();
    return r;
}

__device__ __forceinline__ float blockMax(float v, float* buf) {
#pragma unroll
    for (int o = 16; o > 0; o >>= 1) v = fmaxf(v, __shfl_down_sync(0xffffffffu, v, o));
    int w = threadIdx.x >> 5, l = threadIdx.x & 31;
    if (l == 0) buf[w] = v;
    __syncthreads();
    if (threadIdx.x == 0) {
        float s = buf[0];
#pragma unroll
        for (int i = 1; i < 8; i++) s = fmaxf(s, buf[i]);
        buf[0] = s;
    }
    __syncthreads();
    float r = buf[0];
    __syncthreads();
    return r;
}

// argmax with first-index tie-break
__device__ __forceinline__ int blockArgmax(const float* arr, int L, float* fb, int* ib) {
    float bv = -FLT_MAX; int bi = 0x7FFFFFFF;
    for (int i = threadIdx.x; i < L; i += TPB) {
        float v = arr[i];
        if (v > bv || (v == bv && i < bi)) { bv = v; bi = i; }
    }
#pragma unroll
    for (int o = 16; o > 0; o >>= 1) {
        float ov = __shfl_down_sync(0xffffffffu, bv, o);
        int   oi = __shfl_down_sync(0xffffffffu, bi, o);
        if (ov > bv || (ov == bv && oi < bi)) { bv = ov; bi = oi; }
    }
    int w = threadIdx.x >> 5, l = threadIdx.x & 31;
    if (l == 0) { fb[w] = bv; ib[w] = bi; }
    __syncthreads();
    if (threadIdx.x == 0) {
        float v = fb[0]; int j = ib[0];
#pragma unroll
        for (int i = 1; i < 8; i++)
            if (fb[i] > v || (fb[i] == v && ib[i] < j)) { v = fb[i]; j = ib[i]; }
        ib[0] = j;
    }
    __syncthreads();
    int r = ib[0];
    __syncthreads();
    return r;
}

// ---------------- alignment (padded, branch-free inner loop) ----------------
// xpad: plain zero-padded [240], data at [80,160). yald: dup-padded [480] output.
__device__ __forceinline__ int align_fn(const float* xpad, const float* yr, float ny,
                                        float* sim, float* yald, float* fb, int* ib) {
    int s = threadIdx.x;
    if (s < NSHIFT) {
        float num = 0.f, nx2 = 0.f;
        const float* xp = xpad + s + 1;
#pragma unroll 8
        for (int w = 0; w < 80; w++) {
            float xv = xp[w];
            num = fmaf(xv, yr[w], num);
            nx2 = fmaf(xv, xv, nx2);
        }
        sim[s] = num / (sqrtf(nx2) * ny + 1e-6f);
    }
    __syncthreads();
    int theta = blockArgmax(sim, NSHIFT, fb, ib);
    if (threadIdx.x < IDIM) {
        float v = xpad[theta + (int)threadIdx.x + 1];
        yald[2 * (80 + threadIdx.x)]     = v;
        yald[2 * (80 + threadIdx.x) + 1] = v;
    }
    __syncthreads();
    return theta;
}

// ---------------- encoder chunks (FFMA2) ----------------
// acc[j] accumulates H[sbase+j][{2u,2u+1}] (no bias). xpd: dup-padded [480].
template<int NS>
__device__ __forceinline__ void enc_chunk(const float* __restrict__ We,
                                          const float* xpd, int sbase, int u, u64* acc) {
#pragma unroll
    for (int j = 0; j < NS; j++) acc[j] = 0ull;
    const int r0 = 81 - NS - sbase;                 // first We row
    const u64* wp = reinterpret_cast<const u64*>(We + r0 * 256 + 2 * u);
    const int o0 = 81 - NS;                         // x pair-index base (sbase-independent)
    u64 D[NS];
#pragma unroll
    for (int j = 0; j < NS; j++) D[j] = lds64(xpd, o0 + j);
#pragma unroll 8
    for (int k = 0; k < 80 + NS - 1; k++) {
        u64 wv = wp[k * 128];
#pragma unroll
        for (int j = 0; j < NS; j++) fma2(acc[j], D[j], wv);
#pragma unroll
        for (int j = 0; j < NS - 1; j++) D[j] = D[j + 1];
        D[NS - 1] = lds64(xpd, o0 + k + NS);
    }
}

template<int NS>
__device__ __forceinline__ void enc_energy(const u64* acc, float be0, float be1,
                                           float* psum, int warp, int lane) {
#pragma unroll
    for (int j = 0; j < NS; j++) {
        float lo, hi; unpk(acc[j], lo, hi);
        float v0 = lo + be0, v1 = hi + be1;
        float sq = warpSum(fmaf(v0, v0, v1 * v1));
        if (lane == 0) psum[warp * 16 + j] = sq;
    }
}

// full encoder: writes s_h[256], returns ind (argmax shift)
__device__ __forceinline__ int encode_fn(const float* __restrict__ We, float be0, float be1,
                                         const float* xpd, float* s_h, float* en,
                                         float* psum, float* s_part, float* fb, int* ib) {
    int tid = threadIdx.x;
    int u = tid & 127, g = tid >> 7;
    int warp = tid >> 5, lane = tid & 31;
    u64 acc[16];

    // pass 0: shifts 0..31
    enc_chunk<16>(We, xpd, 16 * g, u, acc);
    enc_energy<16>(acc, be0, be1, psum, warp, lane);
    __syncthreads();
    if (tid < 32) {
        int g2 = tid >> 4, j = tid & 15, w0 = g2 * 4;
        en[tid] = (psum[w0 * 16 + j] + psum[(w0 + 1) * 16 + j]) +
                  (psum[(w0 + 2) * 16 + j] + psum[(w0 + 3) * 16 + j]);
    }
    __syncthreads();

    // pass 1: shifts 32..63
    enc_chunk<16>(We, xpd, 32 + 16 * g, u, acc);
    enc_energy<16>(acc, be0, be1, psum, warp, lane);
    __syncthreads();
    if (tid < 32) {
        int g2 = tid >> 4, j = tid & 15, w0 = g2 * 4;
        en[32 + tid] = (psum[w0 * 16 + j] + psum[(w0 + 1) * 16 + j]) +
                       (psum[(w0 + 2) * 16 + j] + psum[(w0 + 3) * 16 + j]);
    }
    __syncthreads();

    // pass 2: g0 -> shifts 64..72 (NS=9), g1 -> shifts 73..80 (NS=8)
    if (g == 0) {
        enc_chunk<9>(We, xpd, 64, u, acc);
        enc_energy<9>(acc, be0, be1, psum, warp, lane);
    } else {
        enc_chunk<8>(We, xpd, 73, u, acc);
        enc_energy<8>(acc, be0, be1, psum, warp, lane);
    }
    __syncthreads();
    if (tid < 17) {
        if (tid < 9) {
            int j = tid;
            en[64 + j] = (psum[0 * 16 + j] + psum[1 * 16 + j]) +
                         (psum[2 * 16 + j] + psum[3 * 16 + j]);
        } else {
            int j = tid - 9;
            en[73 + j] = (psum[4 * 16 + j] + psum[5 * 16 + j]) +
                         (psum[6 * 16 + j] + psum[7 * 16 + j]);
        }
    }
    __syncthreads();

    int ind = blockArgmax(en, NSENC, fb, ib);

    // recompute H[ind]: 80 rows split 40/40 between groups
    {
        int rs = 80 - ind + 40 * g;
        const u64* wp = reinterpret_cast<const u64*>(We + rs * 256 + 2 * u);
        int ob = 80 + 40 * g;                      // x pair-index base
        u64 a = 0ull;
#pragma unroll 8
        for (int k = 0; k < 40; k++) fma2(a, lds64(xpd, ob + k), wp[k * 128]);
        float lo, hi; unpk(a, lo, hi);
        s_part[g * 256 + 2 * u]     = lo;
        s_part[g * 256 + 2 * u + 1] = hi;
    }
    __syncthreads();
    if (tid < 128) {
        s_h[2 * tid]     = be0 + (s_part[2 * tid]     + s_part[256 + 2 * tid]);
        s_h[2 * tid + 1] = be1 + (s_part[2 * tid + 1] + s_part[256 + 2 * tid + 1]);
    }
    __syncthreads();
    return ind;
}

// ---------------- HSR with compaction ----------------
__device__ __forceinline__ float cmp_rank(float u, float v, int i, int tid) {
    return 0.f; // unused
}

__device__ __forceinline__ int rank_of(const float* sq, float v, int tid) {
    const float4* sq4 = reinterpret_cast<const float4*>(sq);
    int rank = 0;
#pragma unroll 4
    for (int i4 = 0; i4 < 64; i4++) {
        float4 q = sq4[i4];
        int i = 4 * i4;
        rank += (q.x > v || (q.x == v && (i + 0) < tid)) ? 1 : 0;
        rank += (q.y > v || (q.y == v && (i + 1) < tid)) ? 1 : 0;
        rank += (q.z > v || (q.z == v && (i + 2) < tid)) ? 1 : 0;
        rank += (q.w > v || (q.w == v && (i + 3) < tid)) ? 1 : 0;
    }
    return rank;
}

// returns hidden loss; writes 64 compacted (value, rowOffsetBits) into cpk
__device__ __forceinline__ float hsr_fn(const float* hin, float* mp, bool first, bool smt,
                                        float* sq, float* wred, float2* cpk, int* ibuf) {
    int tid = threadIdx.x, lane = tid & 31, wid = tid >> 5;
    float h = hin[tid];
    sq[tid] = h * h;
    __syncthreads();
    bool cur = rank_of(sq, sq[tid], tid) < CDIM;
    float loss = 0.f;
    bool sel; float hval;
    if (first) {
        mp[tid] = cur ? 1.f : 0.f;
        sel = cur; hval = h;
        __syncthreads();
    } else {
        bool prev = mp[tid] > 0.f;
        loss = blockSum((prev && cur && !smt) ? h * h : 0.f, wred);
        float h2 = prev ? 0.f : h;
        __syncthreads();
        sq[tid] = h2 * h2;
        __syncthreads();
        bool cur2 = rank_of(sq, sq[tid], tid) < CDIM;
        if (cur2) mp[tid] += 1.f;
        sel = cur2; hval = h2;
    }
    unsigned bal = __ballot_sync(0xffffffffu, sel);
    if (lane == 0) ibuf[wid] = __popc(bal);
    __syncthreads();
    int base = 0;
#pragma unroll
    for (int w = 0; w < 8; w++) base += (w < wid) ? ibuf[w] : 0;
    int pos = base + __popc(bal & ((1u << lane) - 1u));
    if (sel) cpk[pos] = make_float2(hval, __int_as_float(tid * 160));
    __syncthreads();
    return loss;
}

// ---------------- sparse decode ----------------
__device__ __forceinline__ void decode_fn(const float* __restrict__ W, const float* __restrict__ b,
                                          const float2* cpk, int ind, float* dec, float* dpart) {
    int tid = threadIdx.x;
    if (tid < 240) {
        int seg = tid / 80;
        int d = tid - seg * 80;
        int k0 = (seg == 0) ? 0 : (seg == 1 ? 22 : 43);
        int k1 = (seg == 0) ? 22 : (seg == 1 ? 43 : 64);
        const float* Wb = W + ind + d;
        float a = 0.f;
        for (int k = k0; k < k1; k++) {
            float2 p = cpk[k];
            a = fmaf(p.x, Wb[__float_as_int(p.y)], a);
        }
        dpart[seg * 80 + d] = a;
    }
    __syncthreads();
    if (tid < IDIM)
        dec[tid] = b[ind + tid] + ((dpart[tid] + dpart[80 + tid]) + dpart[160 + tid]);
    __syncthreads();
}

// ---------------- main per-(b,t) kernel ----------------
__global__ void __launch_bounds__(TPB, 2)
net_main(const float* __restrict__ X, const float* __restrict__ Y,
         const float* __restrict__ We, const float* __restrict__ be,
         const float* __restrict__ Wd, const float* __restrict__ bd,
         const float* __restrict__ Wds, const float* __restrict__ bds) {
    __shared__ __align__(16) float s_xres[240];   // plain padded, data at [80,160)
    __shared__ __align__(16) float s_xd[240];     // plain padded
    __shared__ __align__(16) float s_z[240];      // plain padded
    __shared__ __align__(16) float s_xep[480];    // dup padded
    __shared__ __align__(16) float s_yal[480];    // dup padded
    __shared__ __align__(16) float s_y[IDIM];
    __shared__ __align__(16) float s_h[HDIM];
    __shared__ __align__(16) float s_sq[HDIM];
    __shared__ float s_mps[HDIM], s_mpr[HDIM];
    __shared__ float s_en[NSENC];
    __shared__ float s_psum[128];
    __shared__ float s_part[512];
    __shared__ float2 s_cpk[CDIM];
    __shared__ float s_dpart[240];
    __shared__ float s_dec[IDIM];
    __shared__ float s_sim[NSHIFT];
    __shared__ float s_wred[8], s_fb[8];
    __shared__ int   s_ib[8];

    int tid = threadIdx.x;
    int n = blockIdx.x;

    // zero padded buffers (pads stay zero; middles rewritten per use)
    for (int i = tid; i < 480; i += TPB) { s_xep[i] = 0.f; s_yal[i] = 0.f; }
    for (int i = tid; i < 240; i += TPB) { s_xres[i] = 0.f; s_xd[i] = 0.f; s_z[i] = 0.f; }
    s_mps[tid] = 0.f; s_mpr[tid] = 0.f;
    __syncthreads();

    if (tid < IDIM) {
        s_xres[80 + tid] = X[n * IDIM + tid];
        s_y[tid] = Y[n * IDIM + tid];
    }
    __syncthreads();

    float be0 = be[2 * (tid & 127)];
    float be1 = be[2 * (tid & 127) + 1];

    float zc = blockSum((tid < IDIM && s_y[tid] == 0.f) ? 1.f : 0.f, s_wred);
    bool smt = (zc > 79.5f);

    float loss_total = 0.f;

    for (int it = 0; it < NIT; ++it) {
        float ny2 = blockSum((tid < IDIM) ? s_y[tid] * s_y[tid] : 0.f, s_wred);
        float ny = sqrtf(ny2);

        // ---- alignment 1: x_res vs y_res ----
        int theta1 = align_fn(s_xres, s_y, ny, s_sim, s_yal, s_fb, s_ib);

        // ---- attention + reverse shift ----
        float yav = (tid < IDIM) ? s_yal[2 * (80 + tid)] : 0.f;
        float v = (tid < IDIM) ? yav * s_y[tid] : -FLT_MAX;
        float m = blockMax(v, s_wred);
        float e = (tid < IDIM) ? expf(v - m) : 0.f;
        float se = blockSum(e, s_wred);
        if (tid < IDIM) s_z[80 + tid] = yav * (e / se);
        __syncthreads();
        if (tid < IDIM) {
            float xe = s_z[159 - theta1 + tid];
            s_xep[2 * (80 + tid)]     = xe;
            s_xep[2 * (80 + tid) + 1] = xe;
        }
        __syncthreads();

        // ---- self branch ----
        int ind_self = encode_fn(We, be0, be1, s_xep, s_h, s_en, s_psum, s_part, s_fb, s_ib);
        float lh_self = hsr_fn(s_h, s_mps, (it == 0), smt, s_sq, s_wred, s_cpk, s_ib);
        decode_fn(Wds, bds, s_cpk, ind_self, s_dec, s_dpart);

        int move1 = abs(theta1 - (IDIM - 1));
        float llc = 0.f;
        if (tid < IDIM && move1 <= ETH_I && s_y[tid] != 0.f) {
            float df = s_dec[tid] - s_xres[80 + tid];
            llc = (df * df) / ((float)move1 + 1.f);
        }
        float ll_self = blockSum(llc, s_wred);

        if (tid < IDIM) s_xd[80 + tid] = s_dec[tid];
        __syncthreads();

        // ---- alignment 2: decoded x_ele vs y_res ----
        int theta2 = align_fn(s_xd, s_y, ny, s_sim, s_yal, s_fb, s_ib);

        // ---- src branch ----
        int ind_src = encode_fn(We, be0, be1, s_yal, s_h, s_en, s_psum, s_part, s_fb, s_ib);
        float lh_src = hsr_fn(s_h, s_mpr, (it == 0), smt, s_sq, s_wred, s_cpk, s_ib);
        decode_fn(Wd, bd, s_cpk, ind_src, s_dec, s_dpart);

        int move2 = abs(theta2 - (IDIM - 1));
        llc = 0.f;
        if (tid < IDIM && move2 <= ETH_I && s_y[tid] != 0.f) {
            float df = s_dec[tid] - s_y[tid];
            llc = (df * df) / ((float)move2 + 1.f);
        }
        float ll_src = blockSum(llc, s_wred);

        loss_total += ll_self + ll_src + lh_self + lh_src;

        // ---- residual update ----
        if (tid < IDIM) {
            s_y[tid]        -= s_dec[tid];
            s_xres[80 + tid] -= s_xd[80 + tid];
        }
        __syncthreads();
    }

    if (tid == 0) g_partial[n] = loss_total;
}

// ---------------- deterministic final reduction ----------------
__global__ void net_reduce(float* __restrict__ out) {
    __shared__ float buf[8];
    float s = 0.f;
    for (int i = threadIdx.x; i < NPOS; i += 256) s += g_partial[i];
    s = warpSum(s);
    int w = threadIdx.x >> 5, l = threadIdx.x & 31;
    if (l == 0) buf[w] = s;
    __syncthreads();
    if (threadIdx.x == 0) {
        float t = 0.f;
#pragma unroll
        for (int i = 0; i < 8; i++) t += buf[i];
        out[0] = t * 0.25f;
    }
}

extern "C" void kernel_launch(void* const* d_in, const int* in_sizes, int n_in,
                              void* d_out, int out_size) {
    const float* X   = (const float*)d_in[0];
    const float* Y   = (const float*)d_in[1];
    const float* We  = (const float*)d_in[2];
    const float* be  = (const float*)d_in[3];
    const float* Wd  = (const float*)d_in[4];
    const float* bdv = (const float*)d_in[5];
    const float* Wds = (const float*)d_in[6];
    const float* bds = (const float*)d_in[7];
    float* out = (float*)d_out;

    net_main<<<NPOS, TPB>>>(X, Y, We, be, Wd, bdv, Wds, bds);
    net_reduce<<<1, 256>>>(out);
}

// round 5
// speedup vs baseline: 1.0863x; 1.0863x over previous
#include <cuda_runtime.h>
#include <math.h>
#include <float.h>

#define Bb 8
#define Tt 256
#define NPOS (Bb*Tt)     // 2048
#define IDIM 80
#define HDIM 256
#define CDIM 64
#define NIT 4
#define TPB 256
#define NSHIFT 159
#define NSENC 81
#define ETH_I 40

__device__ float g_partial[NPOS];
__device__ float g_gram[80 * 160];   // g_gram[u][r] = sum_h We[r][h]*We[r+u][h], zero-padded
__device__ float g_bcv[160];         // bc[r] = sum_h be[h]*We[r][h]
__device__ float g_cbe;              // ||be||^2

// ---------------- reductions (deterministic) ----------------
__device__ __forceinline__ float warpSum(float v) {
#pragma unroll
    for (int o = 16; o > 0; o >>= 1) v += __shfl_down_sync(0xffffffffu, v, o);
    return v;
}

__device__ __forceinline__ float blockSum(float v, float* buf) {
    v = warpSum(v);
    int w = threadIdx.x >> 5, l = threadIdx.x & 31;
    if (l == 0) buf[w] = v;
    __syncthreads();
    if (threadIdx.x == 0) {
        float s = 0.f;
#pragma unroll
        for (int i = 0; i < 8; i++) s += buf[i];
        buf[0] = s;
    }
    __syncthreads();
    float r = buf[0];
    __syncthreads();
    return r;
}

__device__ __forceinline__ float blockMax(float v, float* buf) {
#pragma unroll
    for (int o = 16; o > 0; o >>= 1) v = fmaxf(v, __shfl_down_sync(0xffffffffu, v, o));
    int w = threadIdx.x >> 5, l = threadIdx.x & 31;
    if (l == 0) buf[w] = v;
    __syncthreads();
    if (threadIdx.x == 0) {
        float s = buf[0];
#pragma unroll
        for (int i = 1; i < 8; i++) s = fmaxf(s, buf[i]);
        buf[0] = s;
    }
    __syncthreads();
    float r = buf[0];
    __syncthreads();
    return r;
}

// argmax with first-index tie-break
__device__ __forceinline__ int blockArgmax(const float* arr, int L, float* fb, int* ib) {
    float bv = -FLT_MAX; int bi = 0x7FFFFFFF;
    for (int i = threadIdx.x; i < L; i += TPB) {
        float v = arr[i];
        if (v > bv || (v == bv && i < bi)) { bv = v; bi = i; }
    }
#pragma unroll
    for (int o = 16; o > 0; o >>= 1) {
        float ov = __shfl_down_sync(0xffffffffu, bv, o);
        int   oi = __shfl_down_sync(0xffffffffu, bi, o);
        if (ov > bv || (ov == bv && oi < bi)) { bv = ov; bi = oi; }
    }
    int w = threadIdx.x >> 5, l = threadIdx.x & 31;
    if (l == 0) { fb[w] = bv; ib[w] = bi; }
    __syncthreads();
    if (threadIdx.x == 0) {
        float v = fb[0]; int j = ib[0];
#pragma unroll
        for (int i = 1; i < 8; i++)
            if (fb[i] > v || (fb[i] == v && ib[i] < j)) { v = fb[i]; j = ib[i]; }
        ib[0] = j;
    }
    __syncthreads();
    int r = ib[0];
    __syncthreads();
    return r;
}

// ---------------- alignment ----------------
// xpad: zero-padded [240], data at [80,160). yal: plain [80] output.
__device__ __forceinline__ int align_fn(const float* xpad, const float* yr, float ny,
                                        float* sim, float* yal, float* fb, int* ib) {
    int s = threadIdx.x;
    if (s < NSHIFT) {
        float num = 0.f, nx2 = 0.f;
        const float* xp = xpad + s + 1;
#pragma unroll 8
        for (int w = 0; w < 80; w++) {
            float xv = xp[w];
            num = fmaf(xv, yr[w], num);
            nx2 = fmaf(xv, xv, nx2);
        }
        sim[s] = num / (sqrtf(nx2) * ny + 1e-6f);
    }
    __syncthreads();
    int theta = blockArgmax(sim, NSHIFT, fb, ib);
    if (threadIdx.x < IDIM)
        yal[threadIdx.x] = xpad[theta + (int)threadIdx.x + 1];
    __syncthreads();
    return theta;
}

// ---------------- correlation accumulate: 16 outputs at t0, one lag ----------------
// gu = g_gram + u*160 + t0 ; qu = packed q row (zero-padded to 16) ; nb = P/16 blocks
__device__ __forceinline__ void corr_acc(float* acc, const float* __restrict__ gu,
                                         const float* qu, int nb) {
    float G[16];
#pragma unroll
    for (int k = 0; k < 16; k++) G[k] = gu[k];
    for (int b = 0; b < nb; b++) {
        int d0 = b << 4;
#pragma unroll
        for (int i = 0; i < 16; i++) {
            float qv = qu[d0 + i];
#pragma unroll
            for (int j = 0; j < 16; j++) acc[j] = fmaf(qv, G[(i + j) & 15], acc[j]);
            G[i] = gu[d0 + i + 16];
        }
    }
}

// ---------------- encoder via Gram energies ----------------
// inp: plain [80] in smem. Writes s_h[256], returns ind (argmax shift).
__device__ __noinline__ int encode_fn(const float* __restrict__ We,
                                      const float* __restrict__ be,
                                      const float* inp, float* q, float* part,
                                      const int* s_bu, const int* s_qo,
                                      float* s_h, float* en, float cbe,
                                      float* fb, int* ib) {
    int tid = threadIdx.x;

    // build q (triangular, rows padded to 16-multiples, pad zero-filled)
    for (int i = tid; i < 3840; i += TPB) {
        int u = s_bu[i >> 4];
        int d = i - s_qo[u];
        float v = 0.f;
        if (d < 80 - u) {
            v = inp[d] * inp[d + u];
            if (u) v += v;     // off-diagonal counted twice
        }
        q[i] = v;
    }
    __syncthreads();

    // pair-items: lags u and 79-u summed together. P(u)+P(79-u)=96 -> uniform cost.
    if (tid < 200) {
        int p = tid / 5, c = tid - 5 * p;
        int t0 = c << 4;
        int u = p, u2 = 79 - p;
        float acc[16];
#pragma unroll
        for (int k = 0; k < 16; k++) acc[k] = 0.f;
        corr_acc(acc, g_gram + u  * 160 + t0, q + s_qo[u],  (95 - u)  >> 4);
        corr_acc(acc, g_gram + u2 * 160 + t0, q + s_qo[u2], (95 - u2) >> 4);
        float* pp = part + p * 81 + t0;
#pragma unroll
        for (int j = 0; j < 16; j++) pp[j] = acc[j];
    } else if (tid < 240) {
        // scalar items: t = 80 for pair p
        int p = tid - 200;
        int u = p, u2 = 79 - p;
        float a = 0.f;
        {
            const float* qu = q + s_qo[u];
            const float* gu = g_gram + u * 160 + 80;
            int P = ((95 - u) >> 4) << 4;
            for (int d = 0; d < P; d++) a = fmaf(qu[d], gu[d], a);
        }
        {
            const float* qu = q + s_qo[u2];
            const float* gu = g_gram + u2 * 160 + 80;
            int P = ((95 - u2) >> 4) << 4;
            for (int d = 0; d < P; d++) a = fmaf(qu[d], gu[d], a);
        }
        part[p * 81 + 80] = a;
    }
    __syncthreads();

    // reduce over pairs + bias-linear term; en[s] = E'[t = 80 - s]
    if (tid <= 80) {
        int t = tid;
        float s = 0.f;
#pragma unroll 4
        for (int p = 0; p < 40; p++) s += part[p * 81 + t];
        float lin = 0.f;
        const float* bc = g_bcv + t;
#pragma unroll 4
        for (int d = 0; d < 80; d++) lin = fmaf(inp[d], bc[d], lin);
        en[80 - t] = cbe + 2.f * lin + s;
    }
    __syncthreads();

    int ind = blockArgmax(en, NSENC, fb, ib);

    // recompute H[ind] exactly (same FMA order as the validated direct method)
    {
        const float* wp = We + (80 - ind) * 256 + tid;
        float a0 = 0.f, a1 = 0.f, a2 = 0.f, a3 = 0.f;
#pragma unroll 4
        for (int d = 0; d < 80; d += 4) {
            a0 = fmaf(inp[d],     wp[(d)     * 256], a0);
            a1 = fmaf(inp[d + 1], wp[(d + 1) * 256], a1);
            a2 = fmaf(inp[d + 2], wp[(d + 2) * 256], a2);
            a3 = fmaf(inp[d + 3], wp[(d + 3) * 256], a3);
        }
        s_h[tid] = be[tid] + ((a0 + a1) + (a2 + a3));
    }
    __syncthreads();
    return ind;
}

// ---------------- HSR ----------------
__device__ __forceinline__ int rank_of(const float* sq, float v, int tid) {
    const float4* sq4 = reinterpret_cast<const float4*>(sq);
    int rank = 0;
#pragma unroll 4
    for (int i4 = 0; i4 < 64; i4++) {
        float4 qv = sq4[i4];
        int i = 4 * i4;
        rank += (qv.x > v || (qv.x == v && (i + 0) < tid)) ? 1 : 0;
        rank += (qv.y > v || (qv.y == v && (i + 1) < tid)) ? 1 : 0;
        rank += (qv.z > v || (qv.z == v && (i + 2) < tid)) ? 1 : 0;
        rank += (qv.w > v || (qv.w == v && (i + 3) < tid)) ? 1 : 0;
    }
    return rank;
}

__device__ __forceinline__ float hsr_fn(const float* hin, float* mp, bool first, bool smt,
                                        float* sq, float* wred, float2* cpk, int* ibuf) {
    int tid = threadIdx.x, lane = tid & 31, wid = tid >> 5;
    float h = hin[tid];
    sq[tid] = h * h;
    __syncthreads();
    bool cur = rank_of(sq, sq[tid], tid) < CDIM;
    float loss = 0.f;
    bool sel; float hval;
    if (first) {
        mp[tid] = cur ? 1.f : 0.f;
        sel = cur; hval = h;
        __syncthreads();
    } else {
        bool prev = mp[tid] > 0.f;
        loss = blockSum((prev && cur && !smt) ? h * h : 0.f, wred);
        float h2 = prev ? 0.f : h;
        __syncthreads();
        sq[tid] = h2 * h2;
        __syncthreads();
        bool cur2 = rank_of(sq, sq[tid], tid) < CDIM;
        if (cur2) mp[tid] += 1.f;
        sel = cur2; hval = h2;
    }
    unsigned bal = __ballot_sync(0xffffffffu, sel);
    if (lane == 0) ibuf[wid] = __popc(bal);
    __syncthreads();
    int base = 0;
#pragma unroll
    for (int w = 0; w < 8; w++) base += (w < wid) ? ibuf[w] : 0;
    int pos = base + __popc(bal & ((1u << lane) - 1u));
    if (sel) cpk[pos] = make_float2(hval, __int_as_float(tid * 160));
    __syncthreads();
    return loss;
}

// ---------------- sparse decode ----------------
__device__ __forceinline__ void decode_fn(const float* __restrict__ W, const float* __restrict__ b,
                                          const float2* cpk, int ind, float* dec, float* dpart) {
    int tid = threadIdx.x;
    if (tid < 240) {
        int seg = tid / 80;
        int d = tid - seg * 80;
        int k0 = (seg == 0) ? 0 : (seg == 1 ? 22 : 43);
        int k1 = (seg == 0) ? 22 : (seg == 1 ? 43 : 64);
        const float* Wb = W + ind + d;
        float a = 0.f;
        for (int k = k0; k < k1; k++) {
            float2 p = cpk[k];
            a = fmaf(p.x, Wb[__float_as_int(p.y)], a);
        }
        dpart[seg * 80 + d] = a;
    }
    __syncthreads();
    if (tid < IDIM)
        dec[tid] = b[ind + tid] + ((dpart[tid] + dpart[80 + tid]) + dpart[160 + tid]);
    __syncthreads();
}

// ---------------- setup: Gram diagonals, bc, ||be||^2 ----------------
__global__ void prep_kernel(const float* __restrict__ We, const float* __restrict__ be) {
    int u = blockIdx.x;
    int warp = threadIdx.x >> 5, lane = threadIdx.x & 31;
    if (u < 80) {
        for (int r = warp; r < 160; r += 8) {
            float s = 0.f;
            if (r < 160 - u) {
                const float* a = We + r * 256;
                const float* b2 = We + (r + u) * 256;
                for (int h = lane; h < 256; h += 32) s = fmaf(a[h], b2[h], s);
            }
            s = warpSum(s);
            if (lane == 0) g_gram[u * 160 + r] = s;
        }
    } else {
        for (int r = warp; r < 160; r += 8) {
            const float* a = We + r * 256;
            float s = 0.f;
            for (int h = lane; h < 256; h += 32) s = fmaf(a[h], be[h], s);
            s = warpSum(s);
            if (lane == 0) g_bcv[r] = s;
        }
        if (warp == 0) {
            float s = 0.f;
            for (int h = lane; h < 256; h += 32) s = fmaf(be[h], be[h], s);
            s = warpSum(s);
            if (lane == 0) g_cbe = s;
        }
    }
}

// ---------------- main per-(b,t) kernel ----------------
__global__ void __launch_bounds__(TPB)
net_main(const float* __restrict__ X, const float* __restrict__ Y,
         const float* __restrict__ We, const float* __restrict__ be,
         const float* __restrict__ Wd, const float* __restrict__ bd,
         const float* __restrict__ Wds, const float* __restrict__ bds) {
    extern __shared__ float dyn[];
    float* q    = dyn;          // 3840 floats
    float* part = dyn + 3840;   // 3240 floats (40 pairs x 81 t)

    __shared__ __align__(16) float s_xres[240];
    __shared__ __align__(16) float s_xd[240];
    __shared__ __align__(16) float s_z[240];
    __shared__ __align__(16) float s_y[IDIM];
    __shared__ __align__(16) float s_yal[IDIM];
    __shared__ __align__(16) float s_xep[IDIM];
    __shared__ __align__(16) float s_dec[IDIM];
    __shared__ __align__(16) float s_h[HDIM];
    __shared__ __align__(16) float s_sq[HDIM];
    __shared__ float s_mps[HDIM], s_mpr[HDIM];
    __shared__ float s_en[NSENC];
    __shared__ float s_sim[NSHIFT];
    __shared__ float s_dpart[240];
    __shared__ float2 s_cpk[CDIM];
    __shared__ float s_wred[8], s_fb[8];
    __shared__ int   s_ib[8];
    __shared__ int   s_bu[240];   // q block -> lag
    __shared__ int   s_qo[80];    // lag -> float offset into q

    int tid = threadIdx.x;
    int n = blockIdx.x;

    // index tables
    if (tid < 240) {
        int bi = tid;
        int g, st;
        if (bi < 80)       { g = 0; st = 0;   }
        else if (bi < 144) { g = 1; st = 80;  }
        else if (bi < 192) { g = 2; st = 144; }
        else if (bi < 224) { g = 3; st = 192; }
        else               { g = 4; st = 224; }
        s_bu[bi] = 16 * g + (bi - st) / (5 - g);
    }
    if (tid < 80) {
        int g = tid >> 4, r = tid & 15;
        int base = 5 * g - (g * (g - 1)) / 2;
        s_qo[tid] = ((base << 4) + r * (5 - g)) << 4;
    }

    for (int i = tid; i < 240; i += TPB) { s_xres[i] = 0.f; s_xd[i] = 0.f; s_z[i] = 0.f; }
    s_mps[tid] = 0.f; s_mpr[tid] = 0.f;
    __syncthreads();

    if (tid < IDIM) {
        s_xres[80 + tid] = X[n * IDIM + tid];
        s_y[tid] = Y[n * IDIM + tid];
    }
    __syncthreads();

    float cbe = g_cbe;

    float zc = blockSum((tid < IDIM && s_y[tid] == 0.f) ? 1.f : 0.f, s_wred);
    bool smt = (zc > 79.5f);

    float loss_total = 0.f;

    for (int it = 0; it < NIT; ++it) {
        float ny2 = blockSum((tid < IDIM) ? s_y[tid] * s_y[tid] : 0.f, s_wred);
        float ny = sqrtf(ny2);

        // ---- alignment 1: x_res vs y_res ----
        int theta1 = align_fn(s_xres, s_y, ny, s_sim, s_yal, s_fb, s_ib);

        // ---- attention + reverse shift ----
        float yav = (tid < IDIM) ? s_yal[tid] : 0.f;
        float v = (tid < IDIM) ? yav * s_y[tid] : -FLT_MAX;
        float m = blockMax(v, s_wred);
        float e = (tid < IDIM) ? expf(v - m) : 0.f;
        float se = blockSum(e, s_wred);
        if (tid < IDIM) s_z[80 + tid] = yav * (e / se);
        __syncthreads();
        if (tid < IDIM) s_xep[tid] = s_z[159 - theta1 + tid];
        __syncthreads();

        // ---- self branch ----
        int ind_self = encode_fn(We, be, s_xep, q, part, s_bu, s_qo, s_h, s_en, cbe, s_fb, s_ib);
        float lh_self = hsr_fn(s_h, s_mps, (it == 0), smt, s_sq, s_wred, s_cpk, s_ib);
        decode_fn(Wds, bds, s_cpk, ind_self, s_dec, s_dpart);

        int move1 = abs(theta1 - (IDIM - 1));
        float llc = 0.f;
        if (tid < IDIM && move1 <= ETH_I && s_y[tid] != 0.f) {
            float df = s_dec[tid] - s_xres[80 + tid];
            llc = (df * df) / ((float)move1 + 1.f);
        }
        float ll_self = blockSum(llc, s_wred);

        if (tid < IDIM) s_xd[80 + tid] = s_dec[tid];
        __syncthreads();

        // ---- alignment 2: decoded x_ele vs y_res ----
        int theta2 = align_fn(s_xd, s_y, ny, s_sim, s_yal, s_fb, s_ib);

        // ---- src branch ----
        int ind_src = encode_fn(We, be, s_yal, q, part, s_bu, s_qo, s_h, s_en, cbe, s_fb, s_ib);
        float lh_src = hsr_fn(s_h, s_mpr, (it == 0), smt, s_sq, s_wred, s_cpk, s_ib);
        decode_fn(Wd, bd, s_cpk, ind_src, s_dec, s_dpart);

        int move2 = abs(theta2 - (IDIM - 1));
        llc = 0.f;
        if (tid < IDIM && move2 <= ETH_I && s_y[tid] != 0.f) {
            float df = s_dec[tid] - s_y[tid];
            llc = (df * df) / ((float)move2 + 1.f);
        }
        float ll_src = blockSum(llc, s_wred);

        loss_total += ll_self + ll_src + lh_self + lh_src;

        // ---- residual update ----
        if (tid < IDIM) {
            s_y[tid]         -= s_dec[tid];
            s_xres[80 + tid] -= s_xd[80 + tid];
        }
        __syncthreads();
    }

    if (tid == 0) g_partial[n] = loss_total;
}

// ---------------- deterministic final reduction ----------------
__global__ void net_reduce(float* __restrict__ out) {
    __shared__ float buf[8];
    float s = 0.f;
    for (int i = threadIdx.x; i < NPOS; i += 256) s += g_partial[i];
    s = warpSum(s);
    int w = threadIdx.x >> 5, l = threadIdx.x & 31;
    if (l == 0) buf[w] = s;
    __syncthreads();
    if (threadIdx.x == 0) {
        float t = 0.f;
#pragma unroll
        for (int i = 0; i < 8; i++) t += buf[i];
        out[0] = t * 0.25f;
    }
}

extern "C" void kernel_launch(void* const* d_in, const int* in_sizes, int n_in,
                              void* d_out, int out_size) {
    const float* X   = (const float*)d_in[0];
    const float* Y   = (const float*)d_in[1];
    const float* We  = (const float*)d_in[2];
    const float* be  = (const float*)d_in[3];
    const float* Wd  = (const float*)d_in[4];
    const float* bdv = (const float*)d_in[5];
    const float* Wds = (const float*)d_in[6];
    const float* bds = (const float*)d_in[7];
    float* out = (float*)d_out;

    const int dyn_bytes = (3840 + 3240) * sizeof(float);   // 28320 B dynamic
    prep_kernel<<<81, 256>>>(We, be);
    net_main<<<NPOS, TPB, dyn_bytes>>>(X, Y, We, be, Wd, bdv, Wds, bds);
    net_reduce<<<1, 256>>>(out);
}

// round 6
// speedup vs baseline: 1.1902x; 1.0957x over previous
#include <cuda_runtime.h>
#include <math.h>
#include <float.h>

#define Bb 8
#define Tt 256
#define NPOS (Bb*Tt)     // 2048
#define IDIM 80
#define HDIM 256
#define CDIM 64
#define NIT 4
#define TPB 256
#define NSHIFT 159
#define NSENC 81
#define ETH_I 40

__device__ float g_partial[NPOS];
__device__ float g_gram[80 * 160];   // u>=1 rows PRE-DOUBLED; zero-padded beyond 160-u
__device__ float g_bcv[160];         // bc[r] = sum_h be[h]*We[r][h]
__device__ float g_cbe;              // ||be||^2

// ---------------- reductions (deterministic, 2-sync) ----------------
__device__ __forceinline__ float warpSum(float v) {
#pragma unroll
    for (int o = 16; o > 0; o >>= 1) v += __shfl_down_sync(0xffffffffu, v, o);
    return v;
}

__device__ __forceinline__ float blockSum(float v, float* buf) {
    v = warpSum(v);
    int w = threadIdx.x >> 5, l = threadIdx.x & 31;
    if (l == 0) buf[w] = v;
    __syncthreads();
    float s = 0.f;
#pragma unroll
    for (int i = 0; i < 8; i++) s += buf[i];   // same order as before -> same bits
    __syncthreads();
    return s;
}

__device__ __forceinline__ float blockMax(float v, float* buf) {
#pragma unroll
    for (int o = 16; o > 0; o >>= 1) v = fmaxf(v, __shfl_down_sync(0xffffffffu, v, o));
    int w = threadIdx.x >> 5, l = threadIdx.x & 31;
    if (l == 0) buf[w] = v;
    __syncthreads();
    float s = buf[0];
#pragma unroll
    for (int i = 1; i < 8; i++) s = fmaxf(s, buf[i]);
    __syncthreads();
    return s;
}

// argmax with first-index tie-break (2 syncs)
__device__ __forceinline__ int blockArgmax(const float* arr, int L, float* fb, int* ib) {
    float bv = -FLT_MAX; int bi = 0x7FFFFFFF;
    for (int i = threadIdx.x; i < L; i += TPB) {
        float v = arr[i];
        if (v > bv || (v == bv && i < bi)) { bv = v; bi = i; }
    }
#pragma unroll
    for (int o = 16; o > 0; o >>= 1) {
        float ov = __shfl_down_sync(0xffffffffu, bv, o);
        int   oi = __shfl_down_sync(0xffffffffu, bi, o);
        if (ov > bv || (ov == bv && oi < bi)) { bv = ov; bi = oi; }
    }
    int w = threadIdx.x >> 5, l = threadIdx.x & 31;
    if (l == 0) { fb[w] = bv; ib[w] = bi; }
    __syncthreads();
    float v = fb[0]; int j = ib[0];
#pragma unroll
    for (int i = 1; i < 8; i++)
        if (fb[i] > v || (fb[i] == v && ib[i] < j)) { v = fb[i]; j = ib[i]; }
    __syncthreads();
    return j;
}

// ---------------- alignment ----------------
// xpad: zero-padded [240], data at [80,160). yal: output [>=80], only [0,80) written.
__device__ __forceinline__ int align_fn(const float* xpad, const float* yr, float ny,
                                        float* sim, float* yal, float* fb, int* ib) {
    int s = threadIdx.x;
    if (s < NSHIFT) {
        float num = 0.f, nx2 = 0.f;
        const float* xp = xpad + s + 1;
#pragma unroll 8
        for (int w = 0; w < 80; w++) {
            float xv = xp[w];
            num = fmaf(xv, yr[w], num);
            nx2 = fmaf(xv, xv, nx2);
        }
        sim[s] = num / (sqrtf(nx2) * ny + 1e-6f);
    }
    __syncthreads();
    int theta = blockArgmax(sim, NSHIFT, fb, ib);
    if (threadIdx.x < IDIM)
        yal[threadIdx.x] = xpad[theta + (int)threadIdx.x + 1];
    __syncthreads();
    return theta;
}

// ---------------- correlation accumulate (q on the fly) ----------------
// q[d] = ipd[d]*ipu[d] (zero beyond valid range via padded input); gram pre-doubled for u>0.
__device__ __forceinline__ void corr_acc(float* acc, const float* __restrict__ gu,
                                         const float* ipd, const float* ipu, int nb) {
    float G[16];
#pragma unroll
    for (int k = 0; k < 16; k++) G[k] = gu[k];
    for (int b = 0; b < nb; b++) {
        int d0 = b << 4;
#pragma unroll
        for (int i = 0; i < 16; i++) {
            float qv = ipd[d0 + i] * ipu[d0 + i];
#pragma unroll
            for (int j = 0; j < 16; j++) acc[j] = fmaf(qv, G[(i + j) & 15], acc[j]);
            G[i] = gu[d0 + i + 16];
        }
    }
}

// ---------------- encoder via Gram energies ----------------
// inp: zero-padded [96] in smem (data [0,80)). Writes s_h[256], returns ind.
__device__ __noinline__ int encode_fn(const float* __restrict__ We,
                                      const float* __restrict__ be,
                                      const float* inp, float* part, float* lin,
                                      float* s_h, float* en, float cbe,
                                      float* fb, int* ib) {
    int tid = threadIdx.x;

    if (tid < 200) {
        // pair-chunk items: lags u and 79-u summed; P(u)+P(79-u)=96 -> uniform cost
        int p = tid / 5, c = tid - 5 * p;
        int t0 = c << 4;
        int u = p, u2 = 79 - p;
        float acc[16];
#pragma unroll
        for (int k = 0; k < 16; k++) acc[k] = 0.f;
        corr_acc(acc, g_gram + u  * 160 + t0, inp, inp + u,  (95 - u)  >> 4);
        corr_acc(acc, g_gram + u2 * 160 + t0, inp, inp + u2, (95 - u2) >> 4);
        float* pp = part + p * 81 + t0;
#pragma unroll
        for (int j = 0; j < 16; j++) pp[j] = acc[j];
    } else if (tid < 240) {
        // scalar items: t = 80 for pair p
        int p = tid - 200;
        int u = p, u2 = 79 - p;
        float a = 0.f;
        {
            const float* gu = g_gram + u * 160 + 80;
            int P = ((95 - u) >> 4) << 4;
            for (int d = 0; d < P; d++) a = fmaf(inp[d] * inp[d + u], gu[d], a);
        }
        {
            const float* gu = g_gram + u2 * 160 + 80;
            int P = ((95 - u2) >> 4) << 4;
            for (int d = 0; d < P; d++) a = fmaf(inp[d] * inp[d + u2], gu[d], a);
        }
        part[p * 81 + 80] = a;
    } else {
        // bias-linear terms in the corr shadow (identical FMA order to before)
        for (int t = tid - 240; t < 81; t += 16) {
            float l = 0.f;
            const float* bc = g_bcv + t;
#pragma unroll 4
            for (int d = 0; d < 80; d++) l = fmaf(inp[d], bc[d], l);
            lin[t] = l;
        }
    }
    __syncthreads();

    // reduce over pairs; en[s] = E'[t = 80 - s]
    if (tid <= 80) {
        int t = tid;
        float s = 0.f;
#pragma unroll 4
        for (int p = 0; p < 40; p++) s += part[p * 81 + t];
        en[80 - t] = cbe + 2.f * lin[t] + s;
    }
    __syncthreads();

    int ind = blockArgmax(en, NSENC, fb, ib);

    // recompute H[ind] exactly (same FMA order as the validated direct method)
    {
        const float* wp = We + (80 - ind) * 256 + tid;
        float a0 = 0.f, a1 = 0.f, a2 = 0.f, a3 = 0.f;
#pragma unroll 4
        for (int d = 0; d < 80; d += 4) {
            a0 = fmaf(inp[d],     wp[(d)     * 256], a0);
            a1 = fmaf(inp[d + 1], wp[(d + 1) * 256], a1);
            a2 = fmaf(inp[d + 2], wp[(d + 2) * 256], a2);
            a3 = fmaf(inp[d + 3], wp[(d + 3) * 256], a3);
        }
        s_h[tid] = be[tid] + ((a0 + a1) + (a2 + a3));
    }
    __syncthreads();
    return ind;
}

// ---------------- HSR ----------------
__device__ __forceinline__ int rank_of(const float* sq, float v, int tid) {
    const float4* sq4 = reinterpret_cast<const float4*>(sq);
    int rank = 0;
#pragma unroll 4
    for (int i4 = 0; i4 < 64; i4++) {
        float4 qv = sq4[i4];
        int i = 4 * i4;
        rank += (qv.x > v || (qv.x == v && (i + 0) < tid)) ? 1 : 0;
        rank += (qv.y > v || (qv.y == v && (i + 1) < tid)) ? 1 : 0;
        rank += (qv.z > v || (qv.z == v && (i + 2) < tid)) ? 1 : 0;
        rank += (qv.w > v || (qv.w == v && (i + 3) < tid)) ? 1 : 0;
    }
    return rank;
}

__device__ __forceinline__ float hsr_fn(const float* hin, float* mp, bool first, bool smt,
                                        float* sq, float* wred, float2* cpk, int* ibuf) {
    int tid = threadIdx.x, lane = tid & 31, wid = tid >> 5;
    float h = hin[tid];
    sq[tid] = h * h;
    __syncthreads();
    bool cur = rank_of(sq, sq[tid], tid) < CDIM;
    float loss = 0.f;
    bool sel; float hval;
    if (first) {
        mp[tid] = cur ? 1.f : 0.f;
        sel = cur; hval = h;
        __syncthreads();
    } else {
        bool prev = mp[tid] > 0.f;
        loss = blockSum((prev && cur && !smt) ? h * h : 0.f, wred);
        float h2 = prev ? 0.f : h;
        __syncthreads();
        sq[tid] = h2 * h2;
        __syncthreads();
        bool cur2 = rank_of(sq, sq[tid], tid) < CDIM;
        if (cur2) mp[tid] += 1.f;
        sel = cur2; hval = h2;
    }
    unsigned bal = __ballot_sync(0xffffffffu, sel);
    if (lane == 0) ibuf[wid] = __popc(bal);
    __syncthreads();
    int base = 0;
#pragma unroll
    for (int w = 0; w < 8; w++) base += (w < wid) ? ibuf[w] : 0;
    int pos = base + __popc(bal & ((1u << lane) - 1u));
    if (sel) cpk[pos] = make_float2(hval, __int_as_float(tid * 160));
    __syncthreads();
    return loss;
}

// ---------------- sparse decode ----------------
__device__ __forceinline__ void decode_fn(const float* __restrict__ W, const float* __restrict__ b,
                                          const float2* cpk, int ind, float* dec, float* dpart) {
    int tid = threadIdx.x;
    if (tid < 240) {
        int seg = tid / 80;
        int d = tid - seg * 80;
        int k0 = (seg == 0) ? 0 : (seg == 1 ? 22 : 43);
        int k1 = (seg == 0) ? 22 : (seg == 1 ? 43 : 64);
        const float* Wb = W + ind + d;
        float a = 0.f;
        for (int k = k0; k < k1; k++) {
            float2 p = cpk[k];
            a = fmaf(p.x, Wb[__float_as_int(p.y)], a);
        }
        dpart[seg * 80 + d] = a;
    }
    __syncthreads();
    if (tid < IDIM)
        dec[tid] = b[ind + tid] + ((dpart[tid] + dpart[80 + tid]) + dpart[160 + tid]);
    __syncthreads();
}

// ---------------- setup: Gram diagonals (u>0 doubled), bc, ||be||^2 ----------------
__global__ void prep_kernel(const float* __restrict__ We, const float* __restrict__ be) {
    int u = blockIdx.x;
    int warp = threadIdx.x >> 5, lane = threadIdx.x & 31;
    if (u < 80) {
        for (int r = warp; r < 160; r += 8) {
            float s = 0.f;
            if (r < 160 - u) {
                const float* a = We + r * 256;
                const float* b2 = We + (r + u) * 256;
                for (int h = lane; h < 256; h += 32) s = fmaf(a[h], b2[h], s);
            }
            s = warpSum(s);
            if (lane == 0) g_gram[u * 160 + r] = (u > 0) ? 2.f * s : s;  // exact x2
        }
    } else {
        for (int r = warp; r < 160; r += 8) {
            const float* a = We + r * 256;
            float s = 0.f;
            for (int h = lane; h < 256; h += 32) s = fmaf(a[h], be[h], s);
            s = warpSum(s);
            if (lane == 0) g_bcv[r] = s;
        }
        if (warp == 0) {
            float s = 0.f;
            for (int h = lane; h < 256; h += 32) s = fmaf(be[h], be[h], s);
            s = warpSum(s);
            if (lane == 0) g_cbe = s;
        }
    }
}

// ---------------- main per-(b,t) kernel ----------------
__global__ void __launch_bounds__(TPB, 4)
net_main(const float* __restrict__ X, const float* __restrict__ Y,
         const float* __restrict__ We, const float* __restrict__ be,
         const float* __restrict__ Wd, const float* __restrict__ bd,
         const float* __restrict__ Wds, const float* __restrict__ bds) {
    __shared__ __align__(16) float s_part[40 * 81];   // 3240
    __shared__ __align__(16) float s_xres[240];
    __shared__ __align__(16) float s_xd[240];
    __shared__ __align__(16) float s_z[240];
    __shared__ __align__(16) float s_y[IDIM];
    __shared__ __align__(16) float s_yal[96];          // padded encode input
    __shared__ __align__(16) float s_xep[96];          // padded encode input
    __shared__ __align__(16) float s_dec[IDIM];
    __shared__ __align__(16) float s_h[HDIM];
    __shared__ __align__(16) float s_sq[HDIM];
    __shared__ float s_mps[HDIM], s_mpr[HDIM];
    __shared__ float s_en[NSENC];
    __shared__ float s_lin[NSENC];
    __shared__ float s_sim[NSHIFT];
    __shared__ float s_dpart[240];
    __shared__ float2 s_cpk[CDIM];
    __shared__ float s_wred[8], s_fb[8];
    __shared__ int   s_ib[8];

    int tid = threadIdx.x;
    int n = blockIdx.x;

    for (int i = tid; i < 240; i += TPB) { s_xres[i] = 0.f; s_xd[i] = 0.f; s_z[i] = 0.f; }
    if (tid < 96) { s_yal[tid] = 0.f; s_xep[tid] = 0.f; }
    s_mps[tid] = 0.f; s_mpr[tid] = 0.f;
    __syncthreads();

    if (tid < IDIM) {
        s_xres[80 + tid] = X[n * IDIM + tid];
        s_y[tid] = Y[n * IDIM + tid];
    }
    __syncthreads();

    float cbe = g_cbe;

    float zc = blockSum((tid < IDIM && s_y[tid] == 0.f) ? 1.f : 0.f, s_wred);
    bool smt = (zc > 79.5f);

    float loss_total = 0.f;

    for (int it = 0; it < NIT; ++it) {
        float ny2 = blockSum((tid < IDIM) ? s_y[tid] * s_y[tid] : 0.f, s_wred);
        float ny = sqrtf(ny2);

        // ---- alignment 1: x_res vs y_res ----
        int theta1 = align_fn(s_xres, s_y, ny, s_sim, s_yal, s_fb, s_ib);

        // ---- attention + reverse shift ----
        float yav = (tid < IDIM) ? s_yal[tid] : 0.f;
        float v = (tid < IDIM) ? yav * s_y[tid] : -FLT_MAX;
        float m = blockMax(v, s_wred);
        float e = (tid < IDIM) ? expf(v - m) : 0.f;
        float se = blockSum(e, s_wred);
        if (tid < IDIM) s_z[80 + tid] = yav * (e / se);
        __syncthreads();
        if (tid < IDIM) s_xep[tid] = s_z[159 - theta1 + tid];
        __syncthreads();

        // ---- self branch ----
        int ind_self = encode_fn(We, be, s_xep, s_part, s_lin, s_h, s_en, cbe, s_fb, s_ib);
        float lh_self = hsr_fn(s_h, s_mps, (it == 0), smt, s_sq, s_wred, s_cpk, s_ib);
        decode_fn(Wds, bds, s_cpk, ind_self, s_dec, s_dpart);

        int move1 = abs(theta1 - (IDIM - 1));
        float llc = 0.f;
        if (tid < IDIM && move1 <= ETH_I && s_y[tid] != 0.f) {
            float df = s_dec[tid] - s_xres[80 + tid];
            llc = (df * df) / ((float)move1 + 1.f);
        }
        float ll_self = blockSum(llc, s_wred);

        if (tid < IDIM) s_xd[80 + tid] = s_dec[tid];
        __syncthreads();

        // ---- alignment 2: decoded x_ele vs y_res ----
        int theta2 = align_fn(s_xd, s_y, ny, s_sim, s_yal, s_fb, s_ib);

        // ---- src branch ----
        int ind_src = encode_fn(We, be, s_yal, s_part, s_lin, s_h, s_en, cbe, s_fb, s_ib);
        float lh_src = hsr_fn(s_h, s_mpr, (it == 0), smt, s_sq, s_wred, s_cpk, s_ib);
        decode_fn(Wd, bd, s_cpk, ind_src, s_dec, s_dpart);

        int move2 = abs(theta2 - (IDIM - 1));
        llc = 0.f;
        if (tid < IDIM && move2 <= ETH_I && s_y[tid] != 0.f) {
            float df = s_dec[tid] - s_y[tid];
            llc = (df * df) / ((float)move2 + 1.f);
        }
        float ll_src = blockSum(llc, s_wred);

        loss_total += ll_self + ll_src + lh_self + lh_src;

        // ---- residual update ----
        if (tid < IDIM) {
            s_y[tid]         -= s_dec[tid];
            s_xres[80 + tid] -= s_xd[80 + tid];
        }
        __syncthreads();
    }

    if (tid == 0) g_partial[n] = loss_total;
}

// ---------------- deterministic final reduction ----------------
__global__ void net_reduce(float* __restrict__ out) {
    __shared__ float buf[8];
    float s = 0.f;
    for (int i = threadIdx.x; i < NPOS; i += 256) s += g_partial[i];
    s = warpSum(s);
    int w = threadIdx.x >> 5, l = threadIdx.x & 31;
    if (l == 0) buf[w] = s;
    __syncthreads();
    if (threadIdx.x == 0) {
        float t = 0.f;
#pragma unroll
        for (int i = 0; i < 8; i++) t += buf[i];
        out[0] = t * 0.25f;
    }
}

extern "C" void kernel_launch(void* const* d_in, const int* in_sizes, int n_in,
                              void* d_out, int out_size) {
    const float* X   = (const float*)d_in[0];
    const float* Y   = (const float*)d_in[1];
    const float* We  = (const float*)d_in[2];
    const float* be  = (const float*)d_in[3];
    const float* Wd  = (const float*)d_in[4];
    const float* bdv = (const float*)d_in[5];
    const float* Wds = (const float*)d_in[6];
    const float* bds = (const float*)d_in[7];
    float* out = (float*)d_out;

    prep_kernel<<<81, 256>>>(We, be);
    net_main<<<NPOS, TPB>>>(X, Y, We, be, Wd, bdv, Wds, bds);
    net_reduce<<<1, 256>>>(out);
}

// round 7
// speedup vs baseline: 1.9502x; 1.6385x over previous
#include <cuda_runtime.h>
#include <math.h>
#include <float.h>

#define Bb 8
#define Tt 256
#define NPOS (Bb*Tt)     // 2048
#define IDIM 80
#define HDIM 256
#define CDIM 64
#define NIT 4
#define TPB 256
#define NSHIFT 159
#define NSENC 81
#define ETH_I 40

__device__ float g_partial[NPOS];
__device__ float g_gram[80 * 160];   // u>=1 rows PRE-DOUBLED; zero-padded beyond 160-u
__device__ float g_bcv[160];         // bc[r] = sum_h be[h]*We[r][h]
__device__ float g_cbe;              // ||be||^2
__device__ float g_G2[128 * 256];    // access-order transposed gram: G2[j][tid]

// ---------------- reductions (deterministic, 2-sync) ----------------
__device__ __forceinline__ float warpSum(float v) {
#pragma unroll
    for (int o = 16; o > 0; o >>= 1) v += __shfl_down_sync(0xffffffffu, v, o);
    return v;
}

__device__ __forceinline__ float blockSum(float v, float* buf) {
    v = warpSum(v);
    int w = threadIdx.x >> 5, l = threadIdx.x & 31;
    if (l == 0) buf[w] = v;
    __syncthreads();
    float s = 0.f;
#pragma unroll
    for (int i = 0; i < 8; i++) s += buf[i];
    __syncthreads();
    return s;
}

__device__ __forceinline__ float blockMax(float v, float* buf) {
#pragma unroll
    for (int o = 16; o > 0; o >>= 1) v = fmaxf(v, __shfl_down_sync(0xffffffffu, v, o));
    int w = threadIdx.x >> 5, l = threadIdx.x & 31;
    if (l == 0) buf[w] = v;
    __syncthreads();
    float s = buf[0];
#pragma unroll
    for (int i = 1; i < 8; i++) s = fmaxf(s, buf[i]);
    __syncthreads();
    return s;
}

// argmax with first-index tie-break (2 syncs)
__device__ __forceinline__ int blockArgmax(const float* arr, int L, float* fb, int* ib) {
    float bv = -FLT_MAX; int bi = 0x7FFFFFFF;
    for (int i = threadIdx.x; i < L; i += TPB) {
        float v = arr[i];
        if (v > bv || (v == bv && i < bi)) { bv = v; bi = i; }
    }
#pragma unroll
    for (int o = 16; o > 0; o >>= 1) {
        float ov = __shfl_down_sync(0xffffffffu, bv, o);
        int   oi = __shfl_down_sync(0xffffffffu, bi, o);
        if (ov > bv || (ov == bv && oi < bi)) { bv = ov; bi = oi; }
    }
    int w = threadIdx.x >> 5, l = threadIdx.x & 31;
    if (l == 0) { fb[w] = bv; ib[w] = bi; }
    __syncthreads();
    float v = fb[0]; int j = ib[0];
#pragma unroll
    for (int i = 1; i < 8; i++)
        if (fb[i] > v || (fb[i] == v && ib[i] < j)) { v = fb[i]; j = ib[i]; }
    __syncthreads();
    return j;
}

// ---------------- alignment ----------------
__device__ __forceinline__ int align_fn(const float* xpad, const float* yr, float ny,
                                        float* sim, float* yal, float* fb, int* ib) {
    int s = threadIdx.x;
    if (s < NSHIFT) {
        float num = 0.f, nx2 = 0.f;
        const float* xp = xpad + s + 1;
#pragma unroll 8
        for (int w = 0; w < 80; w++) {
            float xv = xp[w];
            num = fmaf(xv, yr[w], num);
            nx2 = fmaf(xv, xv, nx2);
        }
        sim[s] = num / (sqrtf(nx2) * ny + 1e-6f);
    }
    __syncthreads();
    int theta = blockArgmax(sim, NSHIFT, fb, ib);
    if (threadIdx.x < IDIM)
        yal[threadIdx.x] = xpad[theta + (int)threadIdx.x + 1];
    __syncthreads();
    return theta;
}

// ---------------- encoder via Gram energies (coalesced G2 stream) ----------------
// inp: zero-padded [96] in smem (data [0,80)). Writes s_h[256], returns ind.
__device__ __noinline__ int encode_fn(const float* __restrict__ We,
                                      const float* __restrict__ be,
                                      const float* inp, float* part, float* lin,
                                      float* s_h, float* en, float cbe,
                                      float* fb, int* ib) {
    int tid = threadIdx.x;

    if (tid < 200) {
        // pair-chunk item: lags u=p and u2=79-p, t-chunk t0=16c. P1+P2=96.
        int p = tid / 5, c = tid - 5 * p;
        int u = p, u2 = 79 - p;
        int P1 = ((95 - u) >> 4) << 4;
        int P2 = 96 - P1;
        const float* gp = g_G2 + tid;     // column stream, stride 256
        float acc[16], G[16];
#pragma unroll
        for (int k = 0; k < 16; k++) acc[k] = 0.f;
        // ---- lag u ----
#pragma unroll
        for (int k = 0; k < 16; k++) { G[k] = *gp; gp += 256; }
        {
            const float* ipu = inp + u;
            for (int b = 0; b < (P1 >> 4); b++) {
                int d0 = b << 4;
#pragma unroll
                for (int i = 0; i < 16; i++) {
                    float qv = inp[d0 + i] * ipu[d0 + i];
#pragma unroll
                    for (int t = 0; t < 16; t++) acc[t] = fmaf(qv, G[(i + t) & 15], acc[t]);
                    G[i] = *gp; gp += 256;
                }
            }
        }
        // ---- lag u2 (ring refill) ----
#pragma unroll
        for (int k = 0; k < 16; k++) { G[k] = *gp; gp += 256; }
        {
            const float* ipu = inp + u2;
            for (int b = 0; b < (P2 >> 4); b++) {
                int d0 = b << 4;
#pragma unroll
                for (int i = 0; i < 16; i++) {
                    float qv = inp[d0 + i] * ipu[d0 + i];
#pragma unroll
                    for (int t = 0; t < 16; t++) acc[t] = fmaf(qv, G[(i + t) & 15], acc[t]);
                    G[i] = *gp; gp += 256;
                }
            }
        }
        float* pp = part + p * 81 + (c << 4);
#pragma unroll
        for (int t = 0; t < 16; t++) pp[t] = acc[t];
    } else if (tid < 240) {
        // scalar item: t = 80 for pair p
        int p = tid - 200;
        int u = p, u2 = 79 - p;
        int P1 = ((95 - u) >> 4) << 4;
        int P2 = 96 - P1;
        const float* gp = g_G2 + tid;
        float a = 0.f;
        {
            const float* ipu = inp + u;
            for (int d = 0; d < P1; d++) { a = fmaf(inp[d] * ipu[d], *gp, a); gp += 256; }
        }
        {
            const float* ipu = inp + u2;
            for (int d = 0; d < P2; d++) { a = fmaf(inp[d] * ipu[d], *gp, a); gp += 256; }
        }
        part[p * 81 + 80] = a;
    } else {
        // bias-linear terms in the corr shadow
        for (int t = tid - 240; t < 81; t += 16) {
            float l = 0.f;
            const float* bc = g_bcv + t;
#pragma unroll 4
            for (int d = 0; d < 80; d++) l = fmaf(inp[d], bc[d], l);
            lin[t] = l;
        }
    }
    __syncthreads();

    // reduce over pairs; en[s] = E'[t = 80 - s]
    if (tid <= 80) {
        int t = tid;
        float s = 0.f;
#pragma unroll 4
        for (int p = 0; p < 40; p++) s += part[p * 81 + t];
        en[80 - t] = cbe + 2.f * lin[t] + s;
    }
    __syncthreads();

    int ind = blockArgmax(en, NSENC, fb, ib);

    // recompute H[ind] exactly
    {
        const float* wp = We + (80 - ind) * 256 + tid;
        float a0 = 0.f, a1 = 0.f, a2 = 0.f, a3 = 0.f;
#pragma unroll 4
        for (int d = 0; d < 80; d += 4) {
            a0 = fmaf(inp[d],     wp[(d)     * 256], a0);
            a1 = fmaf(inp[d + 1], wp[(d + 1) * 256], a1);
            a2 = fmaf(inp[d + 2], wp[(d + 2) * 256], a2);
            a3 = fmaf(inp[d + 3], wp[(d + 3) * 256], a3);
        }
        s_h[tid] = be[tid] + ((a0 + a1) + (a2 + a3));
    }
    __syncthreads();
    return ind;
}

// ---------------- HSR ----------------
__device__ __forceinline__ int rank_of(const float* sq, float v, int tid) {
    const float4* sq4 = reinterpret_cast<const float4*>(sq);
    int rank = 0;
#pragma unroll 4
    for (int i4 = 0; i4 < 64; i4++) {
        float4 qv = sq4[i4];
        int i = 4 * i4;
        rank += (qv.x > v || (qv.x == v && (i + 0) < tid)) ? 1 : 0;
        rank += (qv.y > v || (qv.y == v && (i + 1) < tid)) ? 1 : 0;
        rank += (qv.z > v || (qv.z == v && (i + 2) < tid)) ? 1 : 0;
        rank += (qv.w > v || (qv.w == v && (i + 3) < tid)) ? 1 : 0;
    }
    return rank;
}

__device__ __forceinline__ float hsr_fn(const float* hin, float* mp, bool first, bool smt,
                                        float* sq, float* wred, float2* cpk, int* ibuf) {
    int tid = threadIdx.x, lane = tid & 31, wid = tid >> 5;
    float h = hin[tid];
    sq[tid] = h * h;
    __syncthreads();
    bool cur = rank_of(sq, sq[tid], tid) < CDIM;
    float loss = 0.f;
    bool sel; float hval;
    if (first) {
        mp[tid] = cur ? 1.f : 0.f;
        sel = cur; hval = h;
        __syncthreads();
    } else {
        bool prev = mp[tid] > 0.f;
        loss = blockSum((prev && cur && !smt) ? h * h : 0.f, wred);
        float h2 = prev ? 0.f : h;
        __syncthreads();
        sq[tid] = h2 * h2;
        __syncthreads();
        bool cur2 = rank_of(sq, sq[tid], tid) < CDIM;
        if (cur2) mp[tid] += 1.f;
        sel = cur2; hval = h2;
    }
    unsigned bal = __ballot_sync(0xffffffffu, sel);
    if (lane == 0) ibuf[wid] = __popc(bal);
    __syncthreads();
    int base = 0;
#pragma unroll
    for (int w = 0; w < 8; w++) base += (w < wid) ? ibuf[w] : 0;
    int pos = base + __popc(bal & ((1u << lane) - 1u));
    if (sel) cpk[pos] = make_float2(hval, __int_as_float(tid * 160));
    __syncthreads();
    return loss;
}

// ---------------- sparse decode ----------------
__device__ __forceinline__ void decode_fn(const float* __restrict__ W, const float* __restrict__ b,
                                          const float2* cpk, int ind, float* dec, float* dpart) {
    int tid = threadIdx.x;
    if (tid < 240) {
        int seg = tid / 80;
        int d = tid - seg * 80;
        int k0 = (seg == 0) ? 0 : (seg == 1 ? 22 : 43);
        int k1 = (seg == 0) ? 22 : (seg == 1 ? 43 : 64);
        const float* Wb = W + ind + d;
        float a = 0.f;
        for (int k = k0; k < k1; k++) {
            float2 p = cpk[k];
            a = fmaf(p.x, Wb[__float_as_int(p.y)], a);
        }
        dpart[seg * 80 + d] = a;
    }
    __syncthreads();
    if (tid < IDIM)
        dec[tid] = b[ind + tid] + ((dpart[tid] + dpart[80 + tid]) + dpart[160 + tid]);
    __syncthreads();
}

// ---------------- setup 1: Gram diagonals (u>0 doubled), bc, ||be||^2 ----------------
__global__ void prep_kernel(const float* __restrict__ We, const float* __restrict__ be) {
    int u = blockIdx.x;
    int warp = threadIdx.x >> 5, lane = threadIdx.x & 31;
    if (u < 80) {
        for (int r = warp; r < 160; r += 8) {
            float s = 0.f;
            if (r < 160 - u) {
                const float* a = We + r * 256;
                const float* b2 = We + (r + u) * 256;
                for (int h = lane; h < 256; h += 32) s = fmaf(a[h], b2[h], s);
            }
            s = warpSum(s);
            if (lane == 0) g_gram[u * 160 + r] = (u > 0) ? 2.f * s : s;
        }
    } else {
        for (int r = warp; r < 160; r += 8) {
            const float* a = We + r * 256;
            float s = 0.f;
            for (int h = lane; h < 256; h += 32) s = fmaf(a[h], be[h], s);
            s = warpSum(s);
            if (lane == 0) g_bcv[r] = s;
        }
        if (warp == 0) {
            float s = 0.f;
            for (int h = lane; h < 256; h += 32) s = fmaf(be[h], be[h], s);
            s = warpSum(s);
            if (lane == 0) g_cbe = s;
        }
    }
}

// ---------------- setup 2: access-order transposed gram G2[j][col] ----------------
__global__ void prep2_kernel() {
    int j = blockIdx.x;      // 0..127
    int col = threadIdx.x;   // 0..255
    float v = 0.f;
    if (col < 200) {
        int p = col / 5, c = col - 5 * p;
        int t0 = c << 4;
        int u = p, u2 = 79 - p;
        int P1 = ((95 - u) >> 4) << 4;
        if (j < P1 + 16) v = g_gram[u * 160 + t0 + j];
        else             v = g_gram[u2 * 160 + t0 + (j - P1 - 16)];
    } else if (col < 240) {
        int p = col - 200;
        int u = p, u2 = 79 - p;
        int P1 = ((95 - u) >> 4) << 4;
        int P2 = 96 - P1;
        if (j < P1)            v = g_gram[u * 160 + 80 + j];
        else if (j < P1 + P2)  v = g_gram[u2 * 160 + 80 + (j - P1)];
    }
    g_G2[j * 256 + col] = v;
}

// ---------------- main per-(b,t) kernel ----------------
__global__ void __launch_bounds__(TPB, 4)
net_main(const float* __restrict__ X, const float* __restrict__ Y,
         const float* __restrict__ We, const float* __restrict__ be,
         const float* __restrict__ Wd, const float* __restrict__ bd,
         const float* __restrict__ Wds, const float* __restrict__ bds) {
    __shared__ __align__(16) float s_part[40 * 81];
    __shared__ __align__(16) float s_xres[240];
    __shared__ __align__(16) float s_xd[240];
    __shared__ __align__(16) float s_z[240];
    __shared__ __align__(16) float s_y[IDIM];
    __shared__ __align__(16) float s_yal[96];
    __shared__ __align__(16) float s_xep[96];
    __shared__ __align__(16) float s_dec[IDIM];
    __shared__ __align__(16) float s_h[HDIM];
    __shared__ __align__(16) float s_sq[HDIM];
    __shared__ float s_mps[HDIM], s_mpr[HDIM];
    __shared__ float s_en[NSENC];
    __shared__ float s_lin[NSENC];
    __shared__ float s_sim[NSHIFT];
    __shared__ float s_dpart[240];
    __shared__ float2 s_cpk[CDIM];
    __shared__ float s_wred[8], s_fb[8];
    __shared__ int   s_ib[8];

    int tid = threadIdx.x;
    int n = blockIdx.x;

    for (int i = tid; i < 240; i += TPB) { s_xres[i] = 0.f; s_xd[i] = 0.f; s_z[i] = 0.f; }
    if (tid < 96) { s_yal[tid] = 0.f; s_xep[tid] = 0.f; }
    s_mps[tid] = 0.f; s_mpr[tid] = 0.f;
    __syncthreads();

    if (tid < IDIM) {
        s_xres[80 + tid] = X[n * IDIM + tid];
        s_y[tid] = Y[n * IDIM + tid];
    }
    __syncthreads();

    float cbe = g_cbe;

    float zc = blockSum((tid < IDIM && s_y[tid] == 0.f) ? 1.f : 0.f, s_wred);
    bool smt = (zc > 79.5f);

    float loss_total = 0.f;

    for (int it = 0; it < NIT; ++it) {
        float ny2 = blockSum((tid < IDIM) ? s_y[tid] * s_y[tid] : 0.f, s_wred);
        float ny = sqrtf(ny2);

        // ---- alignment 1: x_res vs y_res ----
        int theta1 = align_fn(s_xres, s_y, ny, s_sim, s_yal, s_fb, s_ib);

        // ---- attention + reverse shift ----
        float yav = (tid < IDIM) ? s_yal[tid] : 0.f;
        float v = (tid < IDIM) ? yav * s_y[tid] : -FLT_MAX;
        float m = blockMax(v, s_wred);
        float e = (tid < IDIM) ? expf(v - m) : 0.f;
        float se = blockSum(e, s_wred);
        if (tid < IDIM) s_z[80 + tid] = yav * (e / se);
        __syncthreads();
        if (tid < IDIM) s_xep[tid] = s_z[159 - theta1 + tid];
        __syncthreads();

        // ---- self branch ----
        int ind_self = encode_fn(We, be, s_xep, s_part, s_lin, s_h, s_en, cbe, s_fb, s_ib);
        float lh_self = hsr_fn(s_h, s_mps, (it == 0), smt, s_sq, s_wred, s_cpk, s_ib);
        decode_fn(Wds, bds, s_cpk, ind_self, s_dec, s_dpart);

        int move1 = abs(theta1 - (IDIM - 1));
        float llc = 0.f;
        if (tid < IDIM && move1 <= ETH_I && s_y[tid] != 0.f) {
            float df = s_dec[tid] - s_xres[80 + tid];
            llc = (df * df) / ((float)move1 + 1.f);
        }
        float ll_self = blockSum(llc, s_wred);

        if (tid < IDIM) s_xd[80 + tid] = s_dec[tid];
        __syncthreads();

        // ---- alignment 2: decoded x_ele vs y_res ----
        int theta2 = align_fn(s_xd, s_y, ny, s_sim, s_yal, s_fb, s_ib);

        // ---- src branch ----
        int ind_src = encode_fn(We, be, s_yal, s_part, s_lin, s_h, s_en, cbe, s_fb, s_ib);
        float lh_src = hsr_fn(s_h, s_mpr, (it == 0), smt, s_sq, s_wred, s_cpk, s_ib);
        decode_fn(Wd, bd, s_cpk, ind_src, s_dec, s_dpart);

        int move2 = abs(theta2 - (IDIM - 1));
        llc = 0.f;
        if (tid < IDIM && move2 <= ETH_I && s_y[tid] != 0.f) {
            float df = s_dec[tid] - s_y[tid];
            llc = (df * df) / ((float)move2 + 1.f);
        }
        float ll_src = blockSum(llc, s_wred);

        loss_total += ll_self + ll_src + lh_self + lh_src;

        // ---- residual update ----
        if (tid < IDIM) {
            s_y[tid]         -= s_dec[tid];
            s_xres[80 + tid] -= s_xd[80 + tid];
        }
        __syncthreads();
    }

    if (tid == 0) g_partial[n] = loss_total;
}

// ---------------- deterministic final reduction ----------------
__global__ void net_reduce(float* __restrict__ out) {
    __shared__ float buf[8];
    float s = 0.f;
    for (int i = threadIdx.x; i < NPOS; i += 256) s += g_partial[i];
    s = warpSum(s);
    int w = threadIdx.x >> 5, l = threadIdx.x & 31;
    if (l == 0) buf[w] = s;
    __syncthreads();
    if (threadIdx.x == 0) {
        float t = 0.f;
#pragma unroll
        for (int i = 0; i < 8; i++) t += buf[i];
        out[0] = t * 0.25f;
    }
}

extern "C" void kernel_launch(void* const* d_in, const int* in_sizes, int n_in,
                              void* d_out, int out_size) {
    const float* X   = (const float*)d_in[0];
    const float* Y   = (const float*)d_in[1];
    const float* We  = (const float*)d_in[2];
    const float* be  = (const float*)d_in[3];
    const float* Wd  = (const float*)d_in[4];
    const float* bdv = (const float*)d_in[5];
    const float* Wds = (const float*)d_in[6];
    const float* bds = (const float*)d_in[7];
    float* out = (float*)d_out;

    prep_kernel<<<81, 256>>>(We, be);
    prep2_kernel<<<128, 256>>>();
    net_main<<<NPOS, TPB>>>(X, Y, We, be, Wd, bdv, Wds, bds);
    net_reduce<<<1, 256>>>(out);
}

// round 8
// speedup vs baseline: 2.1964x; 1.1263x over previous
#include <cuda_runtime.h>
#include <math.h>
#include <float.h>

#define Bb 8
#define Tt 256
#define NPOS (Bb*Tt)     // 2048
#define IDIM 80
#define HDIM 256
#define CDIM 64
#define NIT 4
#define TPB 256
#define NSHIFT 159
#define NSENC 81
#define ETH_I 40

typedef unsigned long long u64;

__device__ float g_partial[NPOS];
__device__ float g_gram[80 * 160];   // u>=1 rows PRE-DOUBLED; zero-padded beyond 160-u
__device__ float g_bcv[160];
__device__ float g_cbe;
__device__ float g_G2[129 * 256];    // access-order transposed gram stream (row 128 = overread pad)

// ---------------- f32x2 helpers ----------------
__device__ __forceinline__ u64 dup2(float x) {
    u64 r; asm("mov.b64 %0, {%1, %1};" : "=l"(r) : "f"(x)); return r;
}
__device__ __forceinline__ u64 pack2(float lo, float hi) {
    u64 r; asm("mov.b64 %0, {%1, %2};" : "=l"(r) : "f"(lo), "f"(hi)); return r;
}
__device__ __forceinline__ void fma2(u64& acc, u64 a, u64 b) {
    asm("fma.rn.f32x2 %0, %1, %2, %0;" : "+l"(acc) : "l"(a), "l"(b));
}
__device__ __forceinline__ void unpk(u64 v, float& lo, float& hi) {
    asm("mov.b64 {%0, %1}, %2;" : "=f"(lo), "=f"(hi) : "l"(v));
}

// ---------------- reductions (deterministic, 2-sync) ----------------
__device__ __forceinline__ float warpSum(float v) {
#pragma unroll
    for (int o = 16; o > 0; o >>= 1) v += __shfl_down_sync(0xffffffffu, v, o);
    return v;
}

__device__ __forceinline__ float blockSum(float v, float* buf) {
    v = warpSum(v);
    int w = threadIdx.x >> 5, l = threadIdx.x & 31;
    if (l == 0) buf[w] = v;
    __syncthreads();
    float s = 0.f;
#pragma unroll
    for (int i = 0; i < 8; i++) s += buf[i];
    __syncthreads();
    return s;
}

__device__ __forceinline__ float blockMax(float v, float* buf) {
#pragma unroll
    for (int o = 16; o > 0; o >>= 1) v = fmaxf(v, __shfl_down_sync(0xffffffffu, v, o));
    int w = threadIdx.x >> 5, l = threadIdx.x & 31;
    if (l == 0) buf[w] = v;
    __syncthreads();
    float s = buf[0];
#pragma unroll
    for (int i = 1; i < 8; i++) s = fmaxf(s, buf[i]);
    __syncthreads();
    return s;
}

__device__ __forceinline__ int blockArgmax(const float* arr, int L, float* fb, int* ib) {
    float bv = -FLT_MAX; int bi = 0x7FFFFFFF;
    for (int i = threadIdx.x; i < L; i += TPB) {
        float v = arr[i];
        if (v > bv || (v == bv && i < bi)) { bv = v; bi = i; }
    }
#pragma unroll
    for (int o = 16; o > 0; o >>= 1) {
        float ov = __shfl_down_sync(0xffffffffu, bv, o);
        int   oi = __shfl_down_sync(0xffffffffu, bi, o);
        if (ov > bv || (ov == bv && oi < bi)) { bv = ov; bi = oi; }
    }
    int w = threadIdx.x >> 5, l = threadIdx.x & 31;
    if (l == 0) { fb[w] = bv; ib[w] = bi; }
    __syncthreads();
    float v = fb[0]; int j = ib[0];
#pragma unroll
    for (int i = 1; i < 8; i++)
        if (fb[i] > v || (fb[i] == v && ib[i] < j)) { v = fb[i]; j = ib[i]; }
    __syncthreads();
    return j;
}

// ---------------- alignment ----------------
__device__ __forceinline__ int align_fn(const float* xpad, const float* yr, float ny,
                                        float* sim, float* yal, float* fb, int* ib) {
    int s = threadIdx.x;
    if (s < NSHIFT) {
        float num = 0.f, nx2 = 0.f;
        const float* xp = xpad + s + 1;
#pragma unroll 8
        for (int w = 0; w < 80; w++) {
            float xv = xp[w];
            num = fmaf(xv, yr[w], num);
            nx2 = fmaf(xv, xv, nx2);
        }
        sim[s] = num / (sqrtf(nx2) * ny + 1e-6f);
    }
    __syncthreads();
    int theta = blockArgmax(sim, NSHIFT, fb, ib);
    if (threadIdx.x < IDIM)
        yal[threadIdx.x] = xpad[theta + (int)threadIdx.x + 1];
    __syncthreads();
    return theta;
}

// ---------------- corr segment (FFMA2, paired-t accumulators) ----------------
// acc2[m] lanes = (acc[t0+2m], acc[t0+2m+1]); per-lane FMA order identical to scalar version.
__device__ __forceinline__ void enc_seg(const float* inp, const float* ipu,
                                        const float* __restrict__ gbase, int joff,
                                        u64* acc2, int nblocks) {
    const float* gp = gbase + joff * 256;
    u64 E[8], O[8];
    float c;
    {   // init window g[0..16] -> 8 even pairs, 8 odd pairs, carry
        float prev = *gp; gp += 256;
#pragma unroll
        for (int k = 0; k < 8; k++) {
            float a = *gp; gp += 256;
            float b = *gp; gp += 256;
            E[k] = pack2(prev, a);
            O[k] = pack2(a, b);
            prev = b;
        }
        c = prev;
    }
    for (int b = 0; b < nblocks; b++) {
        const float* ia = inp + (b << 4);
        const float* ib2 = ipu + (b << 4);
#pragma unroll
        for (int i = 0; i < 16; i++) {
            float qv = ia[i] * ib2[i];
            u64 qd = dup2(qv);
            if ((i & 1) == 0) {
#pragma unroll
                for (int m = 0; m < 8; m++)
                    fma2(acc2[m], qd, E[((i >> 1) + m) & 7]);
                float n = *gp; gp += 256;
                E[(i >> 1) & 7] = pack2(c, n);
                c = n;
            } else {
#pragma unroll
                for (int m = 0; m < 8; m++)
                    fma2(acc2[m], qd, O[((i >> 1) + m) & 7]);
                float n = *gp; gp += 256;
                O[(i >> 1) & 7] = pack2(c, n);
                c = n;
            }
        }
    }
}

// ---------------- encoder via Gram energies ----------------
__device__ __noinline__ int encode_fn(const float* __restrict__ We,
                                      const float* __restrict__ be,
                                      const float* inp, float* part, float* lin,
                                      float* s_h, float* en, float cbe,
                                      float* fb, int* ib) {
    int tid = threadIdx.x;

    if (tid < 200) {
        int p = tid / 5, cch = tid - 5 * p;
        int u = p, u2 = 79 - p;
        int P1 = ((95 - u) >> 4) << 4;
        u64 acc2[8];
#pragma unroll
        for (int m = 0; m < 8; m++) acc2[m] = 0ull;
        const float* gbase = g_G2 + tid;
        enc_seg(inp, inp + u,  gbase, 0,       acc2, P1 >> 4);
        enc_seg(inp, inp + u2, gbase, P1 + 16, acc2, (96 - P1) >> 4);
        float* pp = part + p * 81 + (cch << 4);
#pragma unroll
        for (int m = 0; m < 8; m++) {
            float lo, hi; unpk(acc2[m], lo, hi);
            pp[2 * m]     = lo;
            pp[2 * m + 1] = hi;
        }
    } else if (tid < 240) {
        // scalar item: t = 80 for pair p  (old-style stream layout for these columns)
        int p = tid - 200;
        int u = p, u2 = 79 - p;
        int P1 = ((95 - u) >> 4) << 4;
        int P2 = 96 - P1;
        const float* gp = g_G2 + tid;
        float a = 0.f;
        {
            const float* ipu = inp + u;
            for (int d = 0; d < P1; d++) { a = fmaf(inp[d] * ipu[d], *gp, a); gp += 256; }
        }
        {
            const float* ipu = inp + u2;
            for (int d = 0; d < P2; d++) { a = fmaf(inp[d] * ipu[d], *gp, a); gp += 256; }
        }
        part[p * 81 + 80] = a;
    } else {
        for (int t = tid - 240; t < 81; t += 16) {
            float l = 0.f;
            const float* bc = g_bcv + t;
#pragma unroll 4
            for (int d = 0; d < 80; d++) l = fmaf(inp[d], bc[d], l);
            lin[t] = l;
        }
    }
    __syncthreads();

    if (tid <= 80) {
        int t = tid;
        float s = 0.f;
#pragma unroll 4
        for (int p = 0; p < 40; p++) s += part[p * 81 + t];
        en[80 - t] = cbe + 2.f * lin[t] + s;
    }
    __syncthreads();

    int ind = blockArgmax(en, NSENC, fb, ib);

    // recompute H[ind] exactly
    {
        const float* wp = We + (80 - ind) * 256 + tid;
        float a0 = 0.f, a1 = 0.f, a2 = 0.f, a3 = 0.f;
#pragma unroll 4
        for (int d = 0; d < 80; d += 4) {
            a0 = fmaf(inp[d],     wp[(d)     * 256], a0);
            a1 = fmaf(inp[d + 1], wp[(d + 1) * 256], a1);
            a2 = fmaf(inp[d + 2], wp[(d + 2) * 256], a2);
            a3 = fmaf(inp[d + 3], wp[(d + 3) * 256], a3);
        }
        s_h[tid] = be[tid] + ((a0 + a1) + (a2 + a3));
    }
    __syncthreads();
    return ind;
}

// ---------------- HSR via warp-sorted rank ----------------
__device__ __forceinline__ u64 warp_sort32(u64 key) {
    int lane = threadIdx.x & 31;
#pragma unroll
    for (int k = 2; k <= 32; k <<= 1) {
#pragma unroll
        for (int j = k >> 1; j > 0; j >>= 1) {
            u64 other = __shfl_xor_sync(0xffffffffu, key, j);
            bool up = ((lane & k) == 0);
            bool lower = ((lane & j) == 0);
            bool takeMin = (up == lower);
            u64 mn = (key < other) ? key : other;
            u64 mx = (key < other) ? other : key;
            key = takeMin ? mn : mx;
        }
    }
    return key;   // ascending across lanes
}

// rank = count of keys strictly greater than `key` among all 256 (lists ascending per warp)
__device__ __forceinline__ int rank_sorted(u64 key, const u64* lists) {
    int cle = 0;
#pragma unroll
    for (int w = 0; w < 8; w++) {
        const u64* L = lists + (w << 5);
        int cnt = 0;
#pragma unroll
        for (int step = 16; step > 0; step >>= 1) {
            int t = cnt + step;
            if (t <= 32 && L[t - 1] <= key) cnt = t;
        }
        if (cnt < 32 && L[cnt] <= key) cnt++;
        cle += cnt;
    }
    return 256 - cle;
}

__device__ __forceinline__ u64 make_key(float hq, int tid) {
    return ((u64)__float_as_uint(hq) << 32) | (u64)(255 - tid);
}

__device__ __forceinline__ float hsr_fn(const float* hin, float* mp, bool first, bool smt,
                                        u64* lists, float* wred, float2* cpk, int* ibuf) {
    int tid = threadIdx.x, lane = tid & 31, wid = tid >> 5;
    float h = hin[tid];
    u64 key = make_key(h * h, tid);
    u64 skey = warp_sort32(key);
    lists[(wid << 5) + lane] = skey;
    __syncthreads();
    bool cur = rank_sorted(key, lists) < CDIM;
    float loss = 0.f;
    bool sel; float hval;
    if (first) {
        mp[tid] = cur ? 1.f : 0.f;
        sel = cur; hval = h;
        __syncthreads();
    } else {
        bool prev = mp[tid] > 0.f;
        loss = blockSum((prev && cur && !smt) ? h * h : 0.f, wred);   // syncs inside
        float h2 = prev ? 0.f : h;
        u64 key2 = make_key(h2 * h2, tid);
        u64 skey2 = warp_sort32(key2);
        lists[(wid << 5) + lane] = skey2;   // safe: blockSum synced after all rank reads
        __syncthreads();
        bool cur2 = rank_sorted(key2, lists) < CDIM;
        if (cur2) mp[tid] += 1.f;
        sel = cur2; hval = h2;
    }
    unsigned bal = __ballot_sync(0xffffffffu, sel);
    if (lane == 0) ibuf[wid] = __popc(bal);
    __syncthreads();
    int base = 0;
#pragma unroll
    for (int w = 0; w < 8; w++) base += (w < wid) ? ibuf[w] : 0;
    int pos = base + __popc(bal & ((1u << lane) - 1u));
    if (sel) cpk[pos] = make_float2(hval, __int_as_float(tid * 160));
    __syncthreads();
    return loss;
}

// ---------------- sparse decode ----------------
__device__ __forceinline__ void decode_fn(const float* __restrict__ W, const float* __restrict__ b,
                                          const float2* cpk, int ind, float* dec, float* dpart) {
    int tid = threadIdx.x;
    if (tid < 240) {
        int seg = tid / 80;
        int d = tid - seg * 80;
        int k0 = (seg == 0) ? 0 : (seg == 1 ? 22 : 43);
        int k1 = (seg == 0) ? 22 : (seg == 1 ? 43 : 64);
        const float* Wb = W + ind + d;
        float a = 0.f;
        for (int k = k0; k < k1; k++) {
            float2 p = cpk[k];
            a = fmaf(p.x, Wb[__float_as_int(p.y)], a);
        }
        dpart[seg * 80 + d] = a;
    }
    __syncthreads();
    if (tid < IDIM)
        dec[tid] = b[ind + tid] + ((dpart[tid] + dpart[80 + tid]) + dpart[160 + tid]);
    __syncthreads();
}

// ---------------- setup 1: Gram (u>0 doubled), bc, ||be||^2 ----------------
__global__ void prep_kernel(const float* __restrict__ We, const float* __restrict__ be) {
    int u = blockIdx.x;
    int warp = threadIdx.x >> 5, lane = threadIdx.x & 31;
    if (u < 80) {
        for (int r = warp; r < 160; r += 8) {
            float s = 0.f;
            if (r < 160 - u) {
                const float* a = We + r * 256;
                const float* b2 = We + (r + u) * 256;
                for (int h = lane; h < 256; h += 32) s = fmaf(a[h], b2[h], s);
            }
            s = warpSum(s);
            if (lane == 0) g_gram[u * 160 + r] = (u > 0) ? 2.f * s : s;
        }
    } else {
        for (int r = warp; r < 160; r += 8) {
            const float* a = We + r * 256;
            float s = 0.f;
            for (int h = lane; h < 256; h += 32) s = fmaf(a[h], be[h], s);
            s = warpSum(s);
            if (lane == 0) g_bcv[r] = s;
        }
        if (warp == 0) {
            float s = 0.f;
            for (int h = lane; h < 256; h += 32) s = fmaf(be[h], be[h], s);
            s = warpSum(s);
            if (lane == 0) g_cbe = s;
        }
    }
}

// ---------------- setup 2: G2 stream, new layout ----------------
// cols <200: seg1 rows [0, P1+16): gram[u][t0+j]; seg2 rows [P1+16, 128): gram[u2][t0+j2]
// cols 200-239: rows [0,P1): gram[u][80+j]; [P1, P1+P2): gram[u2][80+(j-P1)]
__global__ void prep2_kernel() {
    int j = blockIdx.x;      // 0..128
    int col = threadIdx.x;
    float v = 0.f;
    if (j < 128) {
        if (col < 200) {
            int p = col / 5, c = col - 5 * p;
            int t0 = c << 4;
            int u = p, u2 = 79 - p;
            int P1 = ((95 - u) >> 4) << 4;
            if (j < P1 + 16) v = g_gram[u * 160 + t0 + j];
            else             v = g_gram[u2 * 160 + t0 + (j - (P1 + 16))];
        } else if (col < 240) {
            int p = col - 200;
            int u = p, u2 = 79 - p;
            int P1 = ((95 - u) >> 4) << 4;
            int P2 = 96 - P1;
            if (j < P1)           v = g_gram[u * 160 + 80 + j];
            else if (j < P1 + P2) v = g_gram[u2 * 160 + 80 + (j - P1)];
        }
    }
    g_G2[j * 256 + col] = v;
}

// ---------------- main per-(b,t) kernel ----------------
__global__ void __launch_bounds__(TPB)
net_main(const float* __restrict__ X, const float* __restrict__ Y,
         const float* __restrict__ We, const float* __restrict__ be,
         const float* __restrict__ Wd, const float* __restrict__ bd,
         const float* __restrict__ Wds, const float* __restrict__ bds) {
    __shared__ __align__(16) float s_part[40 * 81];
    __shared__ __align__(16) float s_xres[240];
    __shared__ __align__(16) float s_xd[240];
    __shared__ __align__(16) float s_z[240];
    __shared__ __align__(16) float s_y[IDIM];
    __shared__ __align__(16) float s_yal[96];
    __shared__ __align__(16) float s_xep[96];
    __shared__ __align__(16) float s_dec[IDIM];
    __shared__ __align__(16) float s_h[HDIM];
    __shared__ __align__(16) u64  s_keys[HDIM];
    __shared__ float s_mps[HDIM], s_mpr[HDIM];
    __shared__ float s_en[NSENC];
    __shared__ float s_lin[NSENC];
    __shared__ float s_sim[NSHIFT];
    __shared__ float s_dpart[240];
    __shared__ float2 s_cpk[CDIM];
    __shared__ float s_wred[8], s_fb[8];
    __shared__ int   s_ib[8];

    int tid = threadIdx.x;
    int n = blockIdx.x;

    for (int i = tid; i < 240; i += TPB) { s_xres[i] = 0.f; s_xd[i] = 0.f; s_z[i] = 0.f; }
    if (tid < 96) { s_yal[tid] = 0.f; s_xep[tid] = 0.f; }
    s_mps[tid] = 0.f; s_mpr[tid] = 0.f;
    __syncthreads();

    if (tid < IDIM) {
        s_xres[80 + tid] = X[n * IDIM + tid];
        s_y[tid] = Y[n * IDIM + tid];
    }
    __syncthreads();

    float cbe = g_cbe;

    float zc = blockSum((tid < IDIM && s_y[tid] == 0.f) ? 1.f : 0.f, s_wred);
    bool smt = (zc > 79.5f);

    float loss_total = 0.f;

    for (int it = 0; it < NIT; ++it) {
        float ny2 = blockSum((tid < IDIM) ? s_y[tid] * s_y[tid] : 0.f, s_wred);
        float ny = sqrtf(ny2);

        // ---- alignment 1: x_res vs y_res ----
        int theta1 = align_fn(s_xres, s_y, ny, s_sim, s_yal, s_fb, s_ib);

        // ---- attention + reverse shift ----
        float yav = (tid < IDIM) ? s_yal[tid] : 0.f;
        float v = (tid < IDIM) ? yav * s_y[tid] : -FLT_MAX;
        float m = blockMax(v, s_wred);
        float e = (tid < IDIM) ? expf(v - m) : 0.f;
        float se = blockSum(e, s_wred);
        if (tid < IDIM) s_z[80 + tid] = yav * (e / se);
        __syncthreads();
        if (tid < IDIM) s_xep[tid] = s_z[159 - theta1 + tid];
        __syncthreads();

        // ---- self branch ----
        int ind_self = encode_fn(We, be, s_xep, s_part, s_lin, s_h, s_en, cbe, s_fb, s_ib);
        float lh_self = hsr_fn(s_h, s_mps, (it == 0), smt, s_keys, s_wred, s_cpk, s_ib);
        decode_fn(Wds, bds, s_cpk, ind_self, s_dec, s_dpart);

        int move1 = abs(theta1 - (IDIM - 1));
        float llc = 0.f;
        if (tid < IDIM && move1 <= ETH_I && s_y[tid] != 0.f) {
            float df = s_dec[tid] - s_xres[80 + tid];
            llc = (df * df) / ((float)move1 + 1.f);
        }
        float ll_self = blockSum(llc, s_wred);

        if (tid < IDIM) s_xd[80 + tid] = s_dec[tid];
        __syncthreads();

        // ---- alignment 2: decoded x_ele vs y_res ----
        int theta2 = align_fn(s_xd, s_y, ny, s_sim, s_yal, s_fb, s_ib);

        // ---- src branch ----
        int ind_src = encode_fn(We, be, s_yal, s_part, s_lin, s_h, s_en, cbe, s_fb, s_ib);
        float lh_src = hsr_fn(s_h, s_mpr, (it == 0), smt, s_keys, s_wred, s_cpk, s_ib);
        decode_fn(Wd, bd, s_cpk, ind_src, s_dec, s_dpart);

        int move2 = abs(theta2 - (IDIM - 1));
        llc = 0.f;
        if (tid < IDIM && move2 <= ETH_I && s_y[tid] != 0.f) {
            float df = s_dec[tid] - s_y[tid];
            llc = (df * df) / ((float)move2 + 1.f);
        }
        float ll_src = blockSum(llc, s_wred);

        loss_total += ll_self + ll_src + lh_self + lh_src;

        // ---- residual update ----
        if (tid < IDIM) {
            s_y[tid]         -= s_dec[tid];
            s_xres[80 + tid] -= s_xd[80 + tid];
        }
        __syncthreads();
    }

    if (tid == 0) g_partial[n] = loss_total;
}

// ---------------- deterministic final reduction ----------------
__global__ void net_reduce(float* __restrict__ out) {
    __shared__ float buf[8];
    float s = 0.f;
    for (int i = threadIdx.x; i < NPOS; i += 256) s += g_partial[i];
    s = warpSum(s);
    int w = threadIdx.x >> 5, l = threadIdx.x & 31;
    if (l == 0) buf[w] = s;
    __syncthreads();
    if (threadIdx.x == 0) {
        float t = 0.f;
#pragma unroll
        for (int i = 0; i < 8; i++) t += buf[i];
        out[0] = t * 0.25f;
    }
}

extern "C" void kernel_launch(void* const* d_in, const int* in_sizes, int n_in,
                              void* d_out, int out_size) {
    const float* X   = (const float*)d_in[0];
    const float* Y   = (const float*)d_in[1];
    const float* We  = (const float*)d_in[2];
    const float* be  = (const float*)d_in[3];
    const float* Wd  = (const float*)d_in[4];
    const float* bdv = (const float*)d_in[5];
    const float* Wds = (const float*)d_in[6];
    const float* bds = (const float*)d_in[7];
    float* out = (float*)d_out;

    prep_kernel<<<81, 256>>>(We, be);
    prep2_kernel<<<129, 256>>>();
    net_main<<<NPOS, TPB>>>(X, Y, We, be, Wd, bdv, Wds, bds);
    net_reduce<<<1, 256>>>(out);
}